// round 12
// baseline (speedup 1.0000x reference)
#include <cuda_runtime.h>
#include <stdint.h>

#define QIN   90
#define QOUT  60
#define OPAD  64
#define OQ    16               // o's per block (quarter)
#define KMAX  16
#define CINV  32
#define COUTV 32
#define H1V   32
#define H2V   64
#define DMAXV 1.0f
#define MAXB  4
#define ROWF  (QIN * CINV)     // 2880 floats per (b,n) row
#define ROWB  (ROWF * 4)       // 11520 bytes per row
#define NRB   4                // rows per iteration
#define NTH   512
#define FB_FLOATS (2 * NRB * ROWF)          // 23040
#define AG_FLOATS (NRB * OQ * CINV)         // 2048
#define WF_FLOATS (CINV * COUTV)            // 1024
#define SMEM_BYTES ((FB_FLOATS + AG_FLOATS + WF_FLOATS) * 4)   // 104448

typedef unsigned long long ull;
// packed f32x2 FMA: acc = a*b + acc (elementwise on two packed floats)
#define FFMA2(acc, a, b) \
    asm("fma.rn.f32x2 %0, %1, %2, %0;" : "+l"(acc) : "l"(a), "l"(b))

// Per-(b,o) compacted tables produced by prep_kernel.
__device__ float          g_Mw[MAXB * OPAD * KMAX * CINV];  // [b][o][k][c], masked weights
__device__ unsigned short g_selo[MAXB * OPAD * KMAX];       // [b][o][k], BYTE offset i*128

// ---------------------------------------------------------------------------
// Kernel 1: distances + top-K selection + WeightNet MLP -> compact tables
// ---------------------------------------------------------------------------
__global__ void prep_kernel(const float* __restrict__ ang_in, const float* __restrict__ ang_out,
                            const float* __restrict__ W1, const float* __restrict__ b1,
                            const float* __restrict__ W2, const float* __restrict__ b2,
                            const float* __restrict__ W3, const float* __restrict__ b3,
                            int B)
{
    int bo = blockIdx.x;
    int b = bo / OPAD, o = bo % OPAD;
    int tid = threadIdx.x;

    if (o >= QOUT) {  // padded o slots: zero weights so main kernel adds nothing
        for (int i = tid; i < KMAX * CINV; i += blockDim.x)
            g_Mw[(b * OPAD + o) * KMAX * CINV + i] = 0.f;
        if (tid < KMAX) g_selo[(b * OPAD + o) * KMAX + tid] = 0;
        return;
    }

    __shared__ float sd[QIN], sbd[QIN];
    __shared__ int   ssel[KMAX];
    __shared__ float smask[KMAX], skd[KMAX], skbd[KMAX];
    __shared__ float sW2[H1V * H2V], sW3[H2V * CINV];
    __shared__ float sW1a[H1V], sW1b[H1V], sb1[H1V], sb2[H2V], sb3[CINV];
    __shared__ float sh1[KMAX][H1V], sh2[KMAX][H2V];

    for (int i = tid; i < H1V * H2V; i += 128) sW2[i] = W2[i];
    for (int i = tid; i < H2V * CINV; i += 128) sW3[i] = W3[i];
    if (tid < H2V) sb2[tid] = b2[tid];
    if (tid < CINV) sb3[tid] = b3[tid];
    if (tid < H1V) { sW1a[tid] = W1[3 * H1V + tid]; sW1b[tid] = W1[4 * H1V + tid]; sb1[tid] = b1[tid]; }

    float aox = ang_out[(b * QOUT + o) * 3 + 0];
    float aoy = ang_out[(b * QOUT + o) * 3 + 1];
    float aoz = ang_out[(b * QOUT + o) * 3 + 2];
    float nout = sqrtf(aox * aox + aoy * aoy + aoz * aoz);
    float ivo = (nout > 0.f) ? 1.f / nout : 0.f;
    float uox = aox * ivo, uoy = aoy * ivo, uoz = aoz * ivo;

    if (tid < QIN) {
        float x = ang_in[(b * QIN + tid) * 3 + 0];
        float y = ang_in[(b * QIN + tid) * 3 + 1];
        float z = ang_in[(b * QIN + tid) * 3 + 2];
        float nin = sqrtf(x * x + y * y + z * z);
        float ivi = (nin > 0.f) ? 1.f / nin : 0.f;
        float dot = (x * ivi) * uox + (y * ivi) * uoy + (z * ivi) * uoz;
        float d = acosf(fminf(fabsf(dot), 1.0f - 1e-7f));
        sd[tid] = d;
        sbd[tid] = nout - nin;
    }
    __syncthreads();

    if (tid < QIN) {
        float dt = sd[tid];
        int r = 0;
        for (int j = 0; j < QIN; j++) {
            float dj = sd[j];
            r += (dj < dt || (dj == dt && j < tid)) ? 1 : 0;
        }
        if (r < KMAX) {
            ssel[r] = tid;
            smask[r] = (dt <= DMAXV) ? 1.f : 0.f;
            skd[r] = dt;
            skbd[r] = sbd[tid];
        }
    }
    __syncthreads();

    int k = tid >> 3, ln = tid & 7;
    {
        float d = skd[k], bd = skbd[k];
        #pragma unroll
        for (int jj = 0; jj < 4; jj++) {
            int j = ln * 4 + jj;
            float h = fmaf(d, sW1a[j], fmaf(bd, sW1b[j], sb1[j]));
            sh1[k][j] = fmaxf(h, 0.f);
        }
    }
    __syncthreads();
    #pragma unroll
    for (int ll = 0; ll < 8; ll++) {
        int l = ln * 8 + ll;
        float acc = sb2[l];
        #pragma unroll 8
        for (int j = 0; j < H1V; j++) acc = fmaf(sh1[k][j], sW2[j * H2V + l], acc);
        sh2[k][l] = fmaxf(acc, 0.f);
    }
    __syncthreads();
    float m = smask[k];
    #pragma unroll
    for (int cc = 0; cc < 4; cc++) {
        int c = ln * 4 + cc;
        float acc = sb3[c];
        #pragma unroll 8
        for (int l = 0; l < H2V; l++) acc = fmaf(sh2[k][l], sW3[l * CINV + c], acc);
        g_Mw[((b * OPAD + o) * KMAX + k) * CINV + c] = m * acc;
    }
    if (ln == 0) g_selo[(b * OPAD + o) * KMAX + k] = (unsigned short)(ssel[k] * 128);
}

// ---------------------------------------------------------------------------
// Kernel 2: persistent gather-conv + Wf epilogue, fp32 f32x2 datapath.
//   2 CTAs/SM x 512 threads (16 warps each), gridDim = (nsm/2, 4 o-quarters)
//   = one wave of 2-CTA slots. CTAs are barrier-independent -> phase overlap.
//   Warp owns ONE o. Half-warp ho handles k of parity ho; lane hl = channel
//   pair (c = 2hl, 2hl+1). Partial sums merged with shfl_xor(16).
// ---------------------------------------------------------------------------
__device__ __forceinline__ void async_rows(float* dst, const float* __restrict__ src,
                                           int nr, int tid)
{
    uint32_t s = (uint32_t)__cvta_generic_to_shared(dst);
    int total = nr * (ROWF / 4);   // float4 count, up to 2880
    #pragma unroll
    for (int i = 0; i < 6; i++) {
        int idx = tid + i * NTH;
        if (idx < total)
            asm volatile("cp.async.cg.shared.global [%0], [%1], 16;\n"
                         :: "r"(s + idx * 16), "l"(src + idx * 4) : "memory");
    }
    asm volatile("cp.async.commit_group;\n" ::: "memory");
}

// Phase 1: gather-reduce, full NRB rows (stale tail rows guarded at store).
// Half-warp ho accumulates k = 2j+ho (j=0..7). Offset for k lives in u32 word
// j (= k>>1) at halfword ho (= k&1). Halves merged via shfl_xor(16); half ho
// stores rows ho*2..ho*2+1 to aggs.
__device__ __forceinline__ void phase1(const char* __restrict__ fbc, float* __restrict__ aggs,
                                       const ull (&Mp)[8], const uint32_t (&ip)[8],
                                       int ogl, int ho, int hl)
{
    ull acc[NRB];
    #pragma unroll
    for (int r = 0; r < NRB; r++) acc[r] = 0ULL;

    const char* lanebase = fbc + hl * 8;
    #pragma unroll
    for (int j = 0; j < 8; j++) {
        int off = (int)((ip[j] >> (ho * 16)) & 0xFFFFu);   // offset of k = 2j+ho
        const char* p = lanebase + off;
        ull m = Mp[j];
        #pragma unroll
        for (int r = 0; r < NRB; r++) {
            ull v = *(const ull*)(p + r * ROWB);   // LDS.64
            FFMA2(acc[r], m, v);
        }
    }
    // Merge even-k and odd-k halves; both halves end with the full sum.
    #pragma unroll
    for (int r = 0; r < NRB; r++) {
        float lo = __uint_as_float((uint32_t)acc[r]);
        float hi = __uint_as_float((uint32_t)(acc[r] >> 32));
        lo += __shfl_xor_sync(0xFFFFFFFFu, lo, 16);
        hi += __shfl_xor_sync(0xFFFFFFFFu, hi, 16);
        if ((r >> 1) == ho) {   // half 0 stores rows 0-1, half 1 rows 2-3
            float2 v; v.x = lo; v.y = hi;
            *(float2*)(aggs + (r * OQ + ogl) * CINV + 2 * hl) = v;   // STS.64
        }
    }
}

__global__ void __launch_bounds__(NTH, 2)
conv_kernel(const float* __restrict__ f_in, const float* __restrict__ Wf,
            const float* __restrict__ bias_out, float* __restrict__ out,
            int B, int N)
{
    extern __shared__ float smem[];
    float* fbuf = smem;                             // [2][NRB * ROWF]
    float* aggs = smem + FB_FLOATS;                 // [NRB][OQ][CINV]
    float* sWf  = smem + FB_FLOATS + AG_FLOATS;     // [CINV][COUTV]

    const int tid   = threadIdx.x;
    const int lane  = tid & 31;
    const int warp  = tid >> 5;          // 0..15
    const int ho    = lane >> 4;         // k-parity half / row-half
    const int hl    = lane & 15;         // channel-pair index (c = 2hl, 2hl+1)
    const int obase = blockIdx.y * OQ;   // this block's o-quarter
    const int ogl   = warp;              // local o 0..15 (one o per warp)

    for (int i = tid; i < WF_FLOATS; i += NTH) sWf[i] = Wf[i];
    const float2 bias2 = ((const float2*)bias_out)[hl];

    long long R = (long long)B * N;
    long long chunk = (R + gridDim.x - 1) / gridDim.x;
    long long r0 = (long long)blockIdx.x * chunk;
    long long r1 = r0 + chunk; if (r1 > R) r1 = R;
    if (r0 >= r1) return;

    ull      Mp[8];
    uint32_t ip[8];

    long long g = r0;
    while (g < r1) {
        int b = (int)(g / N);
        long long gend = (long long)(b + 1) * N; if (gend > r1) gend = r1;

        // Per-batch tables: this half-warp's 8 k's (parity ho), c-pair hl,
        // and all 16 u16 offsets (8 u32 words).
        {
            int og = obase + ogl;
            const ull* mp = (const ull*)(g_Mw + (size_t)(b * OPAD + og) * KMAX * CINV);
            #pragma unroll
            for (int j = 0; j < 8; j++) Mp[j] = mp[(2 * j + ho) * (CINV / 2) + hl];
            const uint32_t* q = (const uint32_t*)&g_selo[(b * OPAD + og) * KMAX];
            #pragma unroll
            for (int j = 0; j < 8; j++) ip[j] = q[j];
        }

        {
            int nfirst = (int)((gend - g) < NRB ? (gend - g) : NRB);
            async_rows(fbuf, f_in + g * ROWF, nfirst, tid);
        }

        int pb = 0;
        for (long long t = g; t < gend; t += NRB, pb ^= 1) {
            long long tn = t + NRB;
            if (tn < gend) {
                int nr = (int)((gend - tn) < NRB ? (gend - tn) : NRB);
                async_rows(fbuf + (pb ^ 1) * (NRB * ROWF), f_in + tn * ROWF, nr, tid);
                asm volatile("cp.async.wait_group 1;\n" ::: "memory");
            } else {
                asm volatile("cp.async.wait_group 0;\n" ::: "memory");
            }
            __syncthreads();   // fbuf[pb] ready for all warps

            const int nrows = (int)((gend - t) < NRB ? (gend - t) : NRB);

            phase1((const char*)(fbuf + pb * (NRB * ROWF)), aggs, Mp, ip, ogl, ho, hl);

            // Block barrier: all warps done reading fbuf[pb] before anyone
            // loops around and prefetches into it next iteration.
            __syncthreads();

            // Phase 2: warp-private aggs -> out. Half ho handles rows ho*2..ho*2+1.
            float ax[2], ay[2];
            #pragma unroll
            for (int rr = 0; rr < 2; rr++) { ax[rr] = bias2.x; ay[rr] = bias2.y; }

            const float* arow = aggs + ogl * CINV;
            const int rb = ho * 2;
            #pragma unroll
            for (int cq = 0; cq < 8; cq++) {
                float2 w0 = ((const float2*)(sWf + (cq * 4 + 0) * COUTV))[hl];
                float2 w1 = ((const float2*)(sWf + (cq * 4 + 1) * COUTV))[hl];
                float2 w2 = ((const float2*)(sWf + (cq * 4 + 2) * COUTV))[hl];
                float2 w3 = ((const float2*)(sWf + (cq * 4 + 3) * COUTV))[hl];
                #pragma unroll
                for (int rr = 0; rr < 2; rr++) {
                    float4 a4 = *(const float4*)(arow + (rb + rr) * (OQ * CINV) + cq * 4);
                    ax[rr] = fmaf(a4.x, w0.x, ax[rr]);  ay[rr] = fmaf(a4.x, w0.y, ay[rr]);
                    ax[rr] = fmaf(a4.y, w1.x, ax[rr]);  ay[rr] = fmaf(a4.y, w1.y, ay[rr]);
                    ax[rr] = fmaf(a4.z, w2.x, ax[rr]);  ay[rr] = fmaf(a4.z, w2.y, ay[rr]);
                    ax[rr] = fmaf(a4.w, w3.x, ax[rr]);  ay[rr] = fmaf(a4.w, w3.y, ay[rr]);
                }
            }

            const int og = obase + ogl;
            if (og < QOUT) {
                #pragma unroll
                for (int rr = 0; rr < 2; rr++) {
                    int r = rb + rr;
                    if (r < nrows) {
                        float2 v; v.x = ax[rr]; v.y = ay[rr];
                        *(float2*)(out + (t + r) * (QOUT * COUTV) + og * COUTV + 2 * hl) = v;
                    }
                }
            }
        }
        g = gend;
    }
}

// ---------------------------------------------------------------------------
extern "C" void kernel_launch(void* const* d_in, const int* in_sizes, int n_in,
                              void* d_out, int out_size)
{
    const float* ang_in   = (const float*)d_in[0];
    const float* ang_out  = (const float*)d_in[1];
    const float* f_in     = (const float*)d_in[2];
    const float* W1       = (const float*)d_in[3];
    const float* b1       = (const float*)d_in[4];
    const float* W2       = (const float*)d_in[5];
    const float* b2       = (const float*)d_in[6];
    const float* W3       = (const float*)d_in[7];
    const float* b3       = (const float*)d_in[8];
    const float* Wf       = (const float*)d_in[9];
    const float* bias_out = (const float*)d_in[10];
    float* out = (float*)d_out;

    int B = in_sizes[0] / (QIN * 3);
    int N = in_sizes[2] / (B * QIN * CINV);

    cudaFuncSetAttribute(conv_kernel, cudaFuncAttributeMaxDynamicSharedMemorySize, SMEM_BYTES);

    prep_kernel<<<B * OPAD, 128>>>(ang_in, ang_out, W1, b1, W2, b2, W3, b3, B);

    int nsm = 148;
    cudaDeviceGetAttribute(&nsm, cudaDevAttrMultiProcessorCount, 0);
    int gx = nsm / 2; if (gx < 1) gx = 1;   // (gx, 4) blocks = 2*nsm -> one 2-CTA wave
    dim3 grid(gx, 4);
    conv_kernel<<<grid, NTH, SMEM_BYTES>>>(f_in, Wf, bias_out, out, B, N);
}

// round 13
// speedup vs baseline: 1.0793x; 1.0793x over previous
#include <cuda_runtime.h>
#include <stdint.h>

#define QIN   90
#define QOUT  60
#define OPAD  64
#define KMAX  16
#define CINV  32
#define COUTV 32
#define H1V   32
#define H2V   64
#define DMAXV 1.0f
#define MAXB  4
#define ROWF  (QIN * CINV)     // 2880 floats per (b,n) row
#define ROWB  (ROWF * 4)
#define NRB   8                // rows per iteration
#define NTH   512
#define FB_FLOATS (2 * NRB * ROWF)
#define AG_FLOATS (NRB * 32 * CINV)
#define WF_FLOATS (CINV * COUTV)
#define SMEM_BYTES ((FB_FLOATS + AG_FLOATS + WF_FLOATS) * 4)   // 221184

typedef unsigned long long ull;
// packed f32x2 FMA: acc = a*b + acc (elementwise on two packed floats)
#define FFMA2(acc, a, b) \
    asm("fma.rn.f32x2 %0, %1, %2, %0;" : "+l"(acc) : "l"(a), "l"(b))

// Per-(b,o) compacted tables produced by prep_kernel.
__device__ float          g_Mw[MAXB * OPAD * KMAX * CINV];  // [b][o][k][c], masked weights
__device__ unsigned short g_selo[MAXB * OPAD * KMAX];       // [b][o][k], BYTE offset i*128

// ---------------------------------------------------------------------------
// Kernel 1: distances + top-K selection + WeightNet MLP -> compact tables
// ---------------------------------------------------------------------------
__global__ void prep_kernel(const float* __restrict__ ang_in, const float* __restrict__ ang_out,
                            const float* __restrict__ W1, const float* __restrict__ b1,
                            const float* __restrict__ W2, const float* __restrict__ b2,
                            const float* __restrict__ W3, const float* __restrict__ b3,
                            int B)
{
    int bo = blockIdx.x;
    int b = bo / OPAD, o = bo % OPAD;
    int tid = threadIdx.x;

    if (o >= QOUT) {  // padded o slots: zero weights so main kernel adds nothing
        for (int i = tid; i < KMAX * CINV; i += blockDim.x)
            g_Mw[(b * OPAD + o) * KMAX * CINV + i] = 0.f;
        if (tid < KMAX) g_selo[(b * OPAD + o) * KMAX + tid] = 0;
        return;
    }

    __shared__ float sd[QIN], sbd[QIN];
    __shared__ int   ssel[KMAX];
    __shared__ float smask[KMAX], skd[KMAX], skbd[KMAX];
    __shared__ float sW2[H1V * H2V], sW3[H2V * CINV];
    __shared__ float sW1a[H1V], sW1b[H1V], sb1[H1V], sb2[H2V], sb3[CINV];
    __shared__ float sh1[KMAX][H1V], sh2[KMAX][H2V];

    for (int i = tid; i < H1V * H2V; i += 128) sW2[i] = W2[i];
    for (int i = tid; i < H2V * CINV; i += 128) sW3[i] = W3[i];
    if (tid < H2V) sb2[tid] = b2[tid];
    if (tid < CINV) sb3[tid] = b3[tid];
    if (tid < H1V) { sW1a[tid] = W1[3 * H1V + tid]; sW1b[tid] = W1[4 * H1V + tid]; sb1[tid] = b1[tid]; }

    float aox = ang_out[(b * QOUT + o) * 3 + 0];
    float aoy = ang_out[(b * QOUT + o) * 3 + 1];
    float aoz = ang_out[(b * QOUT + o) * 3 + 2];
    float nout = sqrtf(aox * aox + aoy * aoy + aoz * aoz);
    float ivo = (nout > 0.f) ? 1.f / nout : 0.f;
    float uox = aox * ivo, uoy = aoy * ivo, uoz = aoz * ivo;

    if (tid < QIN) {
        float x = ang_in[(b * QIN + tid) * 3 + 0];
        float y = ang_in[(b * QIN + tid) * 3 + 1];
        float z = ang_in[(b * QIN + tid) * 3 + 2];
        float nin = sqrtf(x * x + y * y + z * z);
        float ivi = (nin > 0.f) ? 1.f / nin : 0.f;
        float dot = (x * ivi) * uox + (y * ivi) * uoy + (z * ivi) * uoz;
        float d = acosf(fminf(fabsf(dot), 1.0f - 1e-7f));
        sd[tid] = d;
        sbd[tid] = nout - nin;
    }
    __syncthreads();

    if (tid < QIN) {
        float dt = sd[tid];
        int r = 0;
        for (int j = 0; j < QIN; j++) {
            float dj = sd[j];
            r += (dj < dt || (dj == dt && j < tid)) ? 1 : 0;
        }
        if (r < KMAX) {
            ssel[r] = tid;
            smask[r] = (dt <= DMAXV) ? 1.f : 0.f;
            skd[r] = dt;
            skbd[r] = sbd[tid];
        }
    }
    __syncthreads();

    int k = tid >> 3, ln = tid & 7;
    {
        float d = skd[k], bd = skbd[k];
        #pragma unroll
        for (int jj = 0; jj < 4; jj++) {
            int j = ln * 4 + jj;
            float h = fmaf(d, sW1a[j], fmaf(bd, sW1b[j], sb1[j]));
            sh1[k][j] = fmaxf(h, 0.f);
        }
    }
    __syncthreads();
    #pragma unroll
    for (int ll = 0; ll < 8; ll++) {
        int l = ln * 8 + ll;
        float acc = sb2[l];
        #pragma unroll 8
        for (int j = 0; j < H1V; j++) acc = fmaf(sh1[k][j], sW2[j * H2V + l], acc);
        sh2[k][l] = fmaxf(acc, 0.f);
    }
    __syncthreads();
    float m = smask[k];
    #pragma unroll
    for (int cc = 0; cc < 4; cc++) {
        int c = ln * 4 + cc;
        float acc = sb3[c];
        #pragma unroll 8
        for (int l = 0; l < H2V; l++) acc = fmaf(sh2[k][l], sW3[l * CINV + c], acc);
        g_Mw[((b * OPAD + o) * KMAX + k) * CINV + c] = m * acc;
    }
    if (ln == 0) g_selo[(b * OPAD + o) * KMAX + k] = (unsigned short)(ssel[k] * 128);
}

// ---------------------------------------------------------------------------
// Kernel 2: persistent gather-conv + Wf epilogue, packed f32x2 datapath.
//   1 CTA/SM (512 thr, 16 warps), gridDim = (nsm/2, 2 o-halves) -> one wave.
//   Phase 1 (unchanged from the 262us champion): warp covers 2 o's via
//   half-warp split, lane = channel pair, M in regs, cp.async double buffer.
//   Phase 2 (NEW): warp = its 2 o's x 8 rows, lane = c_out, Wf in 32 regs
//   loaded coalesced once per batch -> 8 bcast slots per (o,row) instead of 12.
// ---------------------------------------------------------------------------
__device__ __forceinline__ void async_rows(float* dst, const float* __restrict__ src,
                                           int nr, int tid)
{
    uint32_t s = (uint32_t)__cvta_generic_to_shared(dst);
    int total = nr * (ROWF / 4);   // float4 count, up to 5760
    #pragma unroll
    for (int i = 0; i < 12; i++) {
        int idx = tid + i * NTH;
        if (idx < total)
            asm volatile("cp.async.cg.shared.global [%0], [%1], 16;\n"
                         :: "r"(s + idx * 16), "l"(src + idx * 4) : "memory");
    }
    asm volatile("cp.async.commit_group;\n" ::: "memory");
}

// Phase 1: gather-reduce, always full NRB rows (stale tail rows are computed
// but their stores to gmem are guarded off in phase 2).
__device__ __forceinline__ void phase1(const char* __restrict__ fbc, float* __restrict__ aggs,
                                       const ull (&Mp)[16], const uint32_t (&ip)[8],
                                       int ogl, int hl)
{
    ull acc[NRB];
    #pragma unroll
    for (int r = 0; r < NRB; r++) acc[r] = 0ULL;

    #pragma unroll
    for (int k = 0; k < 16; k++) {
        int off = (int)((ip[k >> 1] >> ((k & 1) * 16)) & 0xFFFFu);
        const char* p = fbc + off + hl * 8;
        ull m = Mp[k];
        #pragma unroll
        for (int r = 0; r < NRB; r++) {
            ull v = *(const ull*)(p + r * ROWB);   // LDS.64
            FFMA2(acc[r], m, v);
        }
    }
    #pragma unroll
    for (int r = 0; r < NRB; r++)
        *(ull*)(aggs + (r * 32 + ogl) * CINV + 2 * hl) = acc[r];   // STS.64
}

__global__ void __launch_bounds__(NTH, 1)
conv_kernel(const float* __restrict__ f_in, const float* __restrict__ Wf,
            const float* __restrict__ bias_out, float* __restrict__ out,
            int B, int N)
{
    extern __shared__ float smem[];
    float* fbuf = smem;                             // [2][NRB * ROWF]
    float* aggs = smem + FB_FLOATS;                 // [NRB][32][CINV]
    float* sWf  = smem + FB_FLOATS + AG_FLOATS;     // [CINV][COUTV]

    const int tid   = threadIdx.x;
    const int lane  = tid & 31;
    const int warp  = tid >> 5;          // 0..15
    const int ho    = lane >> 4;         // which o of the warp's pair (phase 1)
    const int hl    = lane & 15;         // channel-pair index (phase 1)
    const int obase = blockIdx.y * 32;   // this block's o-half
    const int ogl   = warp * 2 + ho;     // phase-1 local o

    for (int i = tid; i < WF_FLOATS; i += NTH) sWf[i] = Wf[i];
    const float biasl = bias_out[lane];  // phase-2: lane = c_out

    long long R = (long long)B * N;
    long long chunk = (R + gridDim.x - 1) / gridDim.x;
    long long r0 = (long long)blockIdx.x * chunk;
    long long r1 = r0 + chunk; if (r1 > R) r1 = R;
    if (r0 >= r1) return;

    ull      Mp[16];
    uint32_t ip[8];

    long long g = r0;
    while (g < r1) {
        int b = (int)(g / N);
        long long gend = (long long)(b + 1) * N; if (gend > r1) gend = r1;

        // Per-batch tables: weights as native float2 (per-channel pair), u16 offsets.
        {
            int og = obase + ogl;
            const ull* mp = (const ull*)(g_Mw + (size_t)(b * OPAD + og) * KMAX * CINV);
            #pragma unroll
            for (int k = 0; k < 16; k++) Mp[k] = mp[k * (CINV / 2) + hl];
            const uint32_t* q = (const uint32_t*)&g_selo[(b * OPAD + og) * KMAX];
            #pragma unroll
            for (int j = 0; j < 8; j++) ip[j] = q[j];
        }

        {
            int nfirst = (int)((gend - g) < NRB ? (gend - g) : NRB);
            async_rows(fbuf, f_in + g * ROWF, nfirst, tid);
        }

        int pb = 0;
        for (long long t = g; t < gend; t += NRB, pb ^= 1) {
            long long tn = t + NRB;
            if (tn < gend) {
                int nr = (int)((gend - tn) < NRB ? (gend - tn) : NRB);
                async_rows(fbuf + (pb ^ 1) * (NRB * ROWF), f_in + tn * ROWF, nr, tid);
                asm volatile("cp.async.wait_group 1;\n" ::: "memory");
            } else {
                asm volatile("cp.async.wait_group 0;\n" ::: "memory");
            }
            __syncthreads();   // batch ready; prev phase2 agg reads done

            const int nrows = (int)((gend - t) < NRB ? (gend - t) : NRB);

            phase1((const char*)(fbuf + pb * (NRB * ROWF)), aggs, Mp, ip, ogl, hl);

            // Block barrier: all warps done reading fbuf[pb] before anyone
            // loops around and prefetches into it. Also publishes aggs.
            __syncthreads();

            // Phase 2 (remapped): lane = c_out, warp covers its 2 o's x rows.
            // Wf column for this lane loaded coalesced into 32 regs per batch.
            float Wfr[CINV];
            #pragma unroll
            for (int c = 0; c < CINV; c++) Wfr[c] = sWf[c * COUTV + lane];

            #pragma unroll
            for (int oo = 0; oo < 2; oo++) {
                const int ol = warp * 2 + oo;
                const int og = obase + ol;
                const float* arow = aggs + ol * CINV;
                if (og < QOUT) {
                    #pragma unroll
                    for (int rg = 0; rg < 2; rg++) {
                        float ax[4];
                        #pragma unroll
                        for (int u = 0; u < 4; u++) ax[u] = biasl;
                        #pragma unroll
                        for (int cq = 0; cq < 8; cq++) {
                            #pragma unroll
                            for (int u = 0; u < 4; u++) {
                                // broadcast LDS.128: all lanes read same 16B
                                float4 a4 = *(const float4*)(arow + (rg * 4 + u) * (32 * CINV) + cq * 4);
                                ax[u] = fmaf(a4.x, Wfr[cq * 4 + 0], ax[u]);
                                ax[u] = fmaf(a4.y, Wfr[cq * 4 + 1], ax[u]);
                                ax[u] = fmaf(a4.z, Wfr[cq * 4 + 2], ax[u]);
                                ax[u] = fmaf(a4.w, Wfr[cq * 4 + 3], ax[u]);
                            }
                        }
                        #pragma unroll
                        for (int u = 0; u < 4; u++) {
                            int r = rg * 4 + u;
                            if (r < nrows)
                                out[(t + r) * (QOUT * COUTV) + og * COUTV + lane] = ax[u];
                        }
                    }
                }
            }
        }
        g = gend;
    }
}

// ---------------------------------------------------------------------------
extern "C" void kernel_launch(void* const* d_in, const int* in_sizes, int n_in,
                              void* d_out, int out_size)
{
    const float* ang_in   = (const float*)d_in[0];
    const float* ang_out  = (const float*)d_in[1];
    const float* f_in     = (const float*)d_in[2];
    const float* W1       = (const float*)d_in[3];
    const float* b1       = (const float*)d_in[4];
    const float* W2       = (const float*)d_in[5];
    const float* b2       = (const float*)d_in[6];
    const float* W3       = (const float*)d_in[7];
    const float* b3       = (const float*)d_in[8];
    const float* Wf       = (const float*)d_in[9];
    const float* bias_out = (const float*)d_in[10];
    float* out = (float*)d_out;

    int B = in_sizes[0] / (QIN * 3);
    int N = in_sizes[2] / (B * QIN * CINV);

    cudaFuncSetAttribute(conv_kernel, cudaFuncAttributeMaxDynamicSharedMemorySize, SMEM_BYTES);

    prep_kernel<<<B * OPAD, 128>>>(ang_in, ang_out, W1, b1, W2, b2, W3, b3, B);

    int nsm = 148;
    cudaDeviceGetAttribute(&nsm, cudaDevAttrMultiProcessorCount, 0);
    int gx = nsm / 2; if (gx < 1) gx = 1;   // (gx, 2) = nsm blocks -> one wave
    dim3 grid(gx, 2);
    conv_kernel<<<grid, NTH, SMEM_BYTES>>>(f_in, Wf, bias_out, out, B, N);
}

// round 14
// speedup vs baseline: 1.2018x; 1.1135x over previous
#include <cuda_runtime.h>
#include <cuda_fp16.h>
#include <stdint.h>

#define QIN   90
#define QOUT  60
#define OPAD  64
#define KMAX  16
#define CINV  32
#define COUTV 32
#define H1V   32
#define H2V   64
#define DMAXV 1.0f
#define MAXB  4
#define ROWF  (QIN * CINV)   // 2880 floats per (b,n) row
#define ROWB  (ROWF * 4)
#define NRB   8              // rows per iteration
#define NTH   512
#define FB_FLOATS (2 * NRB * ROWF)          // 46080
#define AGH_U32   (NRB * 32 * 16)           // 4096  (half2 words)
#define WF_FLOATS (CINV * COUTV)            // 1024
#define SMEM_BYTES (FB_FLOATS * 4 + AGH_U32 * 4 + WF_FLOATS * 4)   // 204800

typedef unsigned long long ull;
// packed f32x2 FMA: acc = a*b + acc (elementwise on two packed floats)
#define FFMA2(acc, a, b) \
    asm("fma.rn.f32x2 %0, %1, %2, %0;" : "+l"(acc) : "l"(a), "l"(b))

// Per-(b,o) compacted tables produced by prep_kernel.
__device__ float          g_Mw[MAXB * OPAD * KMAX * CINV];  // [b][o][k][c], masked weights
__device__ unsigned short g_selo[MAXB * OPAD * KMAX];       // [b][o][k], BYTE offset i*128

// ---------------------------------------------------------------------------
// Kernel 1: distances + top-K selection + WeightNet MLP -> compact tables
// ---------------------------------------------------------------------------
__global__ void prep_kernel(const float* __restrict__ ang_in, const float* __restrict__ ang_out,
                            const float* __restrict__ W1, const float* __restrict__ b1,
                            const float* __restrict__ W2, const float* __restrict__ b2,
                            const float* __restrict__ W3, const float* __restrict__ b3,
                            int B)
{
    int bo = blockIdx.x;
    int b = bo / OPAD, o = bo % OPAD;
    int tid = threadIdx.x;

    if (o >= QOUT) {  // padded o slots: zero weights so main kernel adds nothing
        for (int i = tid; i < KMAX * CINV; i += blockDim.x)
            g_Mw[(b * OPAD + o) * KMAX * CINV + i] = 0.f;
        if (tid < KMAX) g_selo[(b * OPAD + o) * KMAX + tid] = 0;
        return;
    }

    __shared__ float sd[QIN], sbd[QIN];
    __shared__ int   ssel[KMAX];
    __shared__ float smask[KMAX], skd[KMAX], skbd[KMAX];
    __shared__ float sW2[H1V * H2V], sW3[H2V * CINV];
    __shared__ float sW1a[H1V], sW1b[H1V], sb1[H1V], sb2[H2V], sb3[CINV];
    __shared__ float sh1[KMAX][H1V], sh2[KMAX][H2V];

    for (int i = tid; i < H1V * H2V; i += 128) sW2[i] = W2[i];
    for (int i = tid; i < H2V * CINV; i += 128) sW3[i] = W3[i];
    if (tid < H2V) sb2[tid] = b2[tid];
    if (tid < CINV) sb3[tid] = b3[tid];
    if (tid < H1V) { sW1a[tid] = W1[3 * H1V + tid]; sW1b[tid] = W1[4 * H1V + tid]; sb1[tid] = b1[tid]; }

    float aox = ang_out[(b * QOUT + o) * 3 + 0];
    float aoy = ang_out[(b * QOUT + o) * 3 + 1];
    float aoz = ang_out[(b * QOUT + o) * 3 + 2];
    float nout = sqrtf(aox * aox + aoy * aoy + aoz * aoz);
    float ivo = (nout > 0.f) ? 1.f / nout : 0.f;
    float uox = aox * ivo, uoy = aoy * ivo, uoz = aoz * ivo;

    if (tid < QIN) {
        float x = ang_in[(b * QIN + tid) * 3 + 0];
        float y = ang_in[(b * QIN + tid) * 3 + 1];
        float z = ang_in[(b * QIN + tid) * 3 + 2];
        float nin = sqrtf(x * x + y * y + z * z);
        float ivi = (nin > 0.f) ? 1.f / nin : 0.f;
        float dot = (x * ivi) * uox + (y * ivi) * uoy + (z * ivi) * uoz;
        float d = acosf(fminf(fabsf(dot), 1.0f - 1e-7f));
        sd[tid] = d;
        sbd[tid] = nout - nin;
    }
    __syncthreads();

    if (tid < QIN) {
        float dt = sd[tid];
        int r = 0;
        for (int j = 0; j < QIN; j++) {
            float dj = sd[j];
            r += (dj < dt || (dj == dt && j < tid)) ? 1 : 0;
        }
        if (r < KMAX) {
            ssel[r] = tid;
            smask[r] = (dt <= DMAXV) ? 1.f : 0.f;
            skd[r] = dt;
            skbd[r] = sbd[tid];
        }
    }
    __syncthreads();

    int k = tid >> 3, ln = tid & 7;
    {
        float d = skd[k], bd = skbd[k];
        #pragma unroll
        for (int jj = 0; jj < 4; jj++) {
            int j = ln * 4 + jj;
            float h = fmaf(d, sW1a[j], fmaf(bd, sW1b[j], sb1[j]));
            sh1[k][j] = fmaxf(h, 0.f);
        }
    }
    __syncthreads();
    #pragma unroll
    for (int ll = 0; ll < 8; ll++) {
        int l = ln * 8 + ll;
        float acc = sb2[l];
        #pragma unroll 8
        for (int j = 0; j < H1V; j++) acc = fmaf(sh1[k][j], sW2[j * H2V + l], acc);
        sh2[k][l] = fmaxf(acc, 0.f);
    }
    __syncthreads();
    float m = smask[k];
    #pragma unroll
    for (int cc = 0; cc < 4; cc++) {
        int c = ln * 4 + cc;
        float acc = sb3[c];
        #pragma unroll 8
        for (int l = 0; l < H2V; l++) acc = fmaf(sh2[k][l], sW3[l * CINV + c], acc);
        g_Mw[((b * OPAD + o) * KMAX + k) * CINV + c] = m * acc;
    }
    if (ln == 0) g_selo[(b * OPAD + o) * KMAX + k] = (unsigned short)(ssel[k] * 128);
}

// ---------------------------------------------------------------------------
// Kernel 2: persistent gather-conv + Wf epilogue. Exactly the 282us champion
// structure (512 thr, 16 warps, S=2, NRB=8, two barriers per batch), with ONE
// change: aggs stored as half2 -> phase-2 broadcast reads halve (8 channels
// per 16B LDS.128) and agg-STS halves. Accumulation stays fp32 throughout.
// ---------------------------------------------------------------------------
__device__ __forceinline__ void async_rows(float* dst, const float* __restrict__ src,
                                           int nr, int tid)
{
    uint32_t s = (uint32_t)__cvta_generic_to_shared(dst);
    int total = nr * (ROWF / 4);   // float4 count, up to 5760
    #pragma unroll
    for (int i = 0; i < 12; i++) {
        int idx = tid + i * NTH;
        if (idx < total)
            asm volatile("cp.async.cg.shared.global [%0], [%1], 16;\n"
                         :: "r"(s + idx * 16), "l"(src + idx * 4) : "memory");
    }
    asm volatile("cp.async.commit_group;\n" ::: "memory");
}

// Phase 1: gather-reduce, always full NRB rows (stale tail rows are computed
// but their stores to gmem are guarded off in phase 2). Result -> half2 aggs.
__device__ __forceinline__ void phase1(const char* __restrict__ fbc, uint32_t* __restrict__ aggsh,
                                       const ull (&Mp)[16], const uint32_t (&ip)[8],
                                       int ogl, int hl)
{
    ull acc[NRB];
    #pragma unroll
    for (int r = 0; r < NRB; r++) acc[r] = 0ULL;

    #pragma unroll
    for (int k = 0; k < 16; k++) {
        int off = (int)((ip[k >> 1] >> ((k & 1) * 16)) & 0xFFFFu);
        const char* p = fbc + off + hl * 8;
        ull m = Mp[k];
        #pragma unroll
        for (int r = 0; r < NRB; r++) {
            ull v = *(const ull*)(p + r * ROWB);   // LDS.64
            FFMA2(acc[r], m, v);
        }
    }
    #pragma unroll
    for (int r = 0; r < NRB; r++) {
        float lo = __uint_as_float((uint32_t)acc[r]);
        float hi = __uint_as_float((uint32_t)(acc[r] >> 32));
        __half2 h = __floats2half2_rn(lo, hi);
        aggsh[(r * 32 + ogl) * 16 + hl] = *(uint32_t*)&h;   // STS.32, conflict-free
    }
}

__global__ void __launch_bounds__(NTH, 1)
conv_kernel(const float* __restrict__ f_in, const float* __restrict__ Wf,
            const float* __restrict__ bias_out, float* __restrict__ out,
            int B, int N)
{
    extern __shared__ float smem[];
    float*    fbuf  = smem;                                  // [2][NRB * ROWF]
    uint32_t* aggsh = (uint32_t*)(smem + FB_FLOATS);         // [NRB][32][16] half2
    float*    sWf   = (float*)(aggsh + AGH_U32);             // [CINV][COUTV]

    const int tid   = threadIdx.x;
    const int lane  = tid & 31;
    const int warp  = tid >> 5;          // 0..15
    const int ho    = lane >> 4;         // which o of the warp's pair
    const int hl    = lane & 15;         // channel-pair index (c = 2hl, 2hl+1)
    const int obase = blockIdx.y * 32;   // this block's o-half
    const int ogl   = warp * 2 + ho;     // local o 0..31

    for (int i = tid; i < WF_FLOATS; i += NTH) sWf[i] = Wf[i];
    const float2 bias2 = ((const float2*)bias_out)[hl];

    long long R = (long long)B * N;
    long long chunk = (R + gridDim.x - 1) / gridDim.x;
    long long r0 = (long long)blockIdx.x * chunk;
    long long r1 = r0 + chunk; if (r1 > R) r1 = R;
    if (r0 >= r1) return;

    ull      Mp[16];
    uint32_t ip[8];

    long long g = r0;
    while (g < r1) {
        int b = (int)(g / N);
        long long gend = (long long)(b + 1) * N; if (gend > r1) gend = r1;

        // Per-batch tables: weights as native float2 (per-channel pair), u16 offsets.
        {
            int og = obase + ogl;
            const ull* mp = (const ull*)(g_Mw + (size_t)(b * OPAD + og) * KMAX * CINV);
            #pragma unroll
            for (int k = 0; k < 16; k++) Mp[k] = mp[k * (CINV / 2) + hl];
            const uint32_t* q = (const uint32_t*)&g_selo[(b * OPAD + og) * KMAX];
            #pragma unroll
            for (int j = 0; j < 8; j++) ip[j] = q[j];
        }

        {
            int nfirst = (int)((gend - g) < NRB ? (gend - g) : NRB);
            async_rows(fbuf, f_in + g * ROWF, nfirst, tid);
        }

        int pb = 0;
        for (long long t = g; t < gend; t += NRB, pb ^= 1) {
            long long tn = t + NRB;
            if (tn < gend) {
                int nr = (int)((gend - tn) < NRB ? (gend - tn) : NRB);
                async_rows(fbuf + (pb ^ 1) * (NRB * ROWF), f_in + tn * ROWF, nr, tid);
                asm volatile("cp.async.wait_group 1;\n" ::: "memory");
            } else {
                asm volatile("cp.async.wait_group 0;\n" ::: "memory");
            }
            __syncthreads();   // batch ready; prev phase2 agg reads done

            const int nrows = (int)((gend - t) < NRB ? (gend - t) : NRB);

            phase1((const char*)(fbuf + pb * (NRB * ROWF)), aggsh, Mp, ip, ogl, hl);

            // REQUIRED block barrier: all warps done reading fbuf[pb] before any
            // warp loops around and prefetches into it. Also publishes aggs.
            __syncthreads();

            // Phase 2: out[og, 2hl..2hl+1] = bias + sum_c agg[og][c] * Wf[c][2hl..]
            // aggs read as half2: one 16B broadcast = 8 channels.
            float ax[NRB], ay[NRB];
            #pragma unroll
            for (int r = 0; r < NRB; r++) { ax[r] = bias2.x; ay[r] = bias2.y; }

            const uint32_t* arow = aggsh + ogl * 16;
            #pragma unroll
            for (int cq2 = 0; cq2 < 4; cq2++) {
                float2 w0 = ((const float2*)(sWf + (cq2 * 8 + 0) * COUTV))[hl];
                float2 w1 = ((const float2*)(sWf + (cq2 * 8 + 1) * COUTV))[hl];
                float2 w2 = ((const float2*)(sWf + (cq2 * 8 + 2) * COUTV))[hl];
                float2 w3 = ((const float2*)(sWf + (cq2 * 8 + 3) * COUTV))[hl];
                float2 w4 = ((const float2*)(sWf + (cq2 * 8 + 4) * COUTV))[hl];
                float2 w5 = ((const float2*)(sWf + (cq2 * 8 + 5) * COUTV))[hl];
                float2 w6 = ((const float2*)(sWf + (cq2 * 8 + 6) * COUTV))[hl];
                float2 w7 = ((const float2*)(sWf + (cq2 * 8 + 7) * COUTV))[hl];
                #pragma unroll
                for (int r = 0; r < NRB; r++) {
                    uint4 a4 = *(const uint4*)(arow + r * (32 * 16) + cq2 * 4); // LDS.128 bcast
                    float2 f0 = __half22float2(*(__half2*)&a4.x);
                    float2 f1 = __half22float2(*(__half2*)&a4.y);
                    float2 f2 = __half22float2(*(__half2*)&a4.z);
                    float2 f3 = __half22float2(*(__half2*)&a4.w);
                    ax[r] = fmaf(f0.x, w0.x, ax[r]);  ay[r] = fmaf(f0.x, w0.y, ay[r]);
                    ax[r] = fmaf(f0.y, w1.x, ax[r]);  ay[r] = fmaf(f0.y, w1.y, ay[r]);
                    ax[r] = fmaf(f1.x, w2.x, ax[r]);  ay[r] = fmaf(f1.x, w2.y, ay[r]);
                    ax[r] = fmaf(f1.y, w3.x, ax[r]);  ay[r] = fmaf(f1.y, w3.y, ay[r]);
                    ax[r] = fmaf(f2.x, w4.x, ax[r]);  ay[r] = fmaf(f2.x, w4.y, ay[r]);
                    ax[r] = fmaf(f2.y, w5.x, ax[r]);  ay[r] = fmaf(f2.y, w5.y, ay[r]);
                    ax[r] = fmaf(f3.x, w6.x, ax[r]);  ay[r] = fmaf(f3.x, w6.y, ay[r]);
                    ax[r] = fmaf(f3.y, w7.x, ax[r]);  ay[r] = fmaf(f3.y, w7.y, ay[r]);
                }
            }

            const int og = obase + ogl;
            if (og < QOUT) {
                #pragma unroll
                for (int r = 0; r < NRB; r++) {
                    if (r < nrows) {
                        float2 v; v.x = ax[r]; v.y = ay[r];
                        *(float2*)(out + (t + r) * (QOUT * COUTV) + og * COUTV + 2 * hl) = v;
                    }
                }
            }
        }
        g = gend;
    }
}

// ---------------------------------------------------------------------------
extern "C" void kernel_launch(void* const* d_in, const int* in_sizes, int n_in,
                              void* d_out, int out_size)
{
    const float* ang_in   = (const float*)d_in[0];
    const float* ang_out  = (const float*)d_in[1];
    const float* f_in     = (const float*)d_in[2];
    const float* W1       = (const float*)d_in[3];
    const float* b1       = (const float*)d_in[4];
    const float* W2       = (const float*)d_in[5];
    const float* b2       = (const float*)d_in[6];
    const float* W3       = (const float*)d_in[7];
    const float* b3       = (const float*)d_in[8];
    const float* Wf       = (const float*)d_in[9];
    const float* bias_out = (const float*)d_in[10];
    float* out = (float*)d_out;

    int B = in_sizes[0] / (QIN * 3);
    int N = in_sizes[2] / (B * QIN * CINV);

    cudaFuncSetAttribute(conv_kernel, cudaFuncAttributeMaxDynamicSharedMemorySize, SMEM_BYTES);

    prep_kernel<<<B * OPAD, 128>>>(ang_in, ang_out, W1, b1, W2, b2, W3, b3, B);

    int nsm = 148;
    cudaDeviceGetAttribute(&nsm, cudaDevAttrMultiProcessorCount, 0);
    int gx = nsm / 2; if (gx < 1) gx = 1;   // (gx, 2) = nsm blocks -> one wave
    dim3 grid(gx, 2);
    conv_kernel<<<grid, NTH, SMEM_BYTES>>>(f_in, Wf, bias_out, out, B, N);
}

// round 15
// speedup vs baseline: 1.7295x; 1.4391x over previous
#include <cuda_runtime.h>
#include <cuda_fp16.h>
#include <stdint.h>

#define QIN   90
#define QOUT  60
#define OPAD  64
#define KMAX  16
#define CINV  32
#define COUTV 32
#define H1V   32
#define H2V   64
#define DMAXV 1.0f
#define MAXB  4
#define ROWF  (QIN * CINV)   // 2880 floats per (b,n) row
#define ROWB  (ROWF * 4)
#define NRB   8              // rows per iteration
#define NTH   512
#define FB_FLOATS (2 * NRB * ROWF)              // 46080 floats = 184320 B
#define AG_STRIDE_W 20                          // 80 B per M-row (conflict-free LDSM)
#define AG_WORDS  (16 * 16 * AG_STRIDE_W)       // 16 warps x 16 Mrows x 20 words = 5120
#define WF_FLOATS (CINV * COUTV)                // 1024
#define SMEM_BYTES (FB_FLOATS * 4 + AG_WORDS * 4 + WF_FLOATS * 4)   // 208896

typedef unsigned long long ull;
// packed f32x2 FMA: acc = a*b + acc (elementwise on two packed floats)
#define FFMA2(acc, a, b) \
    asm("fma.rn.f32x2 %0, %1, %2, %0;" : "+l"(acc) : "l"(a), "l"(b))

// Per-(b,o) compacted tables produced by prep_kernel.
__device__ float          g_Mw[MAXB * OPAD * KMAX * CINV];  // [b][o][k][c], masked weights
__device__ unsigned short g_selo[MAXB * OPAD * KMAX];       // [b][o][k], BYTE offset i*128

// ---------------------------------------------------------------------------
// Kernel 1: distances + top-K selection + WeightNet MLP -> compact tables
// ---------------------------------------------------------------------------
__global__ void prep_kernel(const float* __restrict__ ang_in, const float* __restrict__ ang_out,
                            const float* __restrict__ W1, const float* __restrict__ b1,
                            const float* __restrict__ W2, const float* __restrict__ b2,
                            const float* __restrict__ W3, const float* __restrict__ b3,
                            int B)
{
    int bo = blockIdx.x;
    int b = bo / OPAD, o = bo % OPAD;
    int tid = threadIdx.x;

    if (o >= QOUT) {  // padded o slots: zero weights so main kernel adds nothing
        for (int i = tid; i < KMAX * CINV; i += blockDim.x)
            g_Mw[(b * OPAD + o) * KMAX * CINV + i] = 0.f;
        if (tid < KMAX) g_selo[(b * OPAD + o) * KMAX + tid] = 0;
        return;
    }

    __shared__ float sd[QIN], sbd[QIN];
    __shared__ int   ssel[KMAX];
    __shared__ float smask[KMAX], skd[KMAX], skbd[KMAX];
    __shared__ float sW2[H1V * H2V], sW3[H2V * CINV];
    __shared__ float sW1a[H1V], sW1b[H1V], sb1[H1V], sb2[H2V], sb3[CINV];
    __shared__ float sh1[KMAX][H1V], sh2[KMAX][H2V];

    for (int i = tid; i < H1V * H2V; i += 128) sW2[i] = W2[i];
    for (int i = tid; i < H2V * CINV; i += 128) sW3[i] = W3[i];
    if (tid < H2V) sb2[tid] = b2[tid];
    if (tid < CINV) sb3[tid] = b3[tid];
    if (tid < H1V) { sW1a[tid] = W1[3 * H1V + tid]; sW1b[tid] = W1[4 * H1V + tid]; sb1[tid] = b1[tid]; }

    float aox = ang_out[(b * QOUT + o) * 3 + 0];
    float aoy = ang_out[(b * QOUT + o) * 3 + 1];
    float aoz = ang_out[(b * QOUT + o) * 3 + 2];
    float nout = sqrtf(aox * aox + aoy * aoy + aoz * aoz);
    float ivo = (nout > 0.f) ? 1.f / nout : 0.f;
    float uox = aox * ivo, uoy = aoy * ivo, uoz = aoz * ivo;

    if (tid < QIN) {
        float x = ang_in[(b * QIN + tid) * 3 + 0];
        float y = ang_in[(b * QIN + tid) * 3 + 1];
        float z = ang_in[(b * QIN + tid) * 3 + 2];
        float nin = sqrtf(x * x + y * y + z * z);
        float ivi = (nin > 0.f) ? 1.f / nin : 0.f;
        float dot = (x * ivi) * uox + (y * ivi) * uoy + (z * ivi) * uoz;
        float d = acosf(fminf(fabsf(dot), 1.0f - 1e-7f));
        sd[tid] = d;
        sbd[tid] = nout - nin;
    }
    __syncthreads();

    if (tid < QIN) {
        float dt = sd[tid];
        int r = 0;
        for (int j = 0; j < QIN; j++) {
            float dj = sd[j];
            r += (dj < dt || (dj == dt && j < tid)) ? 1 : 0;
        }
        if (r < KMAX) {
            ssel[r] = tid;
            smask[r] = (dt <= DMAXV) ? 1.f : 0.f;
            skd[r] = dt;
            skbd[r] = sbd[tid];
        }
    }
    __syncthreads();

    int k = tid >> 3, ln = tid & 7;
    {
        float d = skd[k], bd = skbd[k];
        #pragma unroll
        for (int jj = 0; jj < 4; jj++) {
            int j = ln * 4 + jj;
            float h = fmaf(d, sW1a[j], fmaf(bd, sW1b[j], sb1[j]));
            sh1[k][j] = fmaxf(h, 0.f);
        }
    }
    __syncthreads();
    #pragma unroll
    for (int ll = 0; ll < 8; ll++) {
        int l = ln * 8 + ll;
        float acc = sb2[l];
        #pragma unroll 8
        for (int j = 0; j < H1V; j++) acc = fmaf(sh1[k][j], sW2[j * H2V + l], acc);
        sh2[k][l] = fmaxf(acc, 0.f);
    }
    __syncthreads();
    float m = smask[k];
    #pragma unroll
    for (int cc = 0; cc < 4; cc++) {
        int c = ln * 4 + cc;
        float acc = sb3[c];
        #pragma unroll 8
        for (int l = 0; l < H2V; l++) acc = fmaf(sh2[k][l], sW3[l * CINV + c], acc);
        g_Mw[((b * OPAD + o) * KMAX + k) * CINV + c] = m * acc;
    }
    if (ln == 0) g_selo[(b * OPAD + o) * KMAX + k] = (unsigned short)(ssel[k] * 128);
}

// ---------------------------------------------------------------------------
// Kernel 2: champion gather (fp32, f32x2) + HMMA epilogue.
//   512 thr / 16 warps / 1 CTA/SM, grid (nsm/2, 2 o-halves) = one wave.
//   Phase 1: identical to 282us champion; acc stored as half2 into a per-warp
//   16x32 fp16 A-tile (Mrow = ho*8 + r, stride 80 B -> conflict-free LDSM).
//   Phase 2: D[16x32] = A[16x32 fp16] x Wf[32x32 fp16] via 8x mma.m16n8k16,
//   Wf fragments + bias in persistent registers, fp32 accumulate.
// ---------------------------------------------------------------------------
__device__ __forceinline__ void async_rows(float* dst, const float* __restrict__ src,
                                           int nr, int tid)
{
    uint32_t s = (uint32_t)__cvta_generic_to_shared(dst);
    int total = nr * (ROWF / 4);   // float4 count, up to 5760
    #pragma unroll
    for (int i = 0; i < 12; i++) {
        int idx = tid + i * NTH;
        if (idx < total)
            asm volatile("cp.async.cg.shared.global [%0], [%1], 16;\n"
                         :: "r"(s + idx * 16), "l"(src + idx * 4) : "memory");
    }
    asm volatile("cp.async.commit_group;\n" ::: "memory");
}

// Phase 1: gather-reduce (identical to champion), result -> fp16 A-tile.
__device__ __forceinline__ void phase1(const char* __restrict__ fbc, uint32_t* __restrict__ atile,
                                       const ull (&Mp)[16], const uint32_t (&ip)[8],
                                       int ho, int hl)
{
    ull acc[NRB];
    #pragma unroll
    for (int r = 0; r < NRB; r++) acc[r] = 0ULL;

    #pragma unroll
    for (int k = 0; k < 16; k++) {
        int off = (int)((ip[k >> 1] >> ((k & 1) * 16)) & 0xFFFFu);
        const char* p = fbc + off + hl * 8;
        ull m = Mp[k];
        #pragma unroll
        for (int r = 0; r < NRB; r++) {
            ull v = *(const ull*)(p + r * ROWB);   // LDS.64
            FFMA2(acc[r], m, v);
        }
    }
    #pragma unroll
    for (int r = 0; r < NRB; r++) {
        float lo = __uint_as_float((uint32_t)acc[r]);
        float hi = __uint_as_float((uint32_t)(acc[r] >> 32));
        __half2 h = __floats2half2_rn(lo, hi);
        atile[(ho * 8 + r) * AG_STRIDE_W + hl] = *(uint32_t*)&h;   // STS.32
    }
}

__global__ void __launch_bounds__(NTH, 1)
conv_kernel(const float* __restrict__ f_in, const float* __restrict__ Wf,
            const float* __restrict__ bias_out, float* __restrict__ out,
            int B, int N)
{
    extern __shared__ float smem[];
    float*    fbuf  = smem;                                  // [2][NRB * ROWF]
    uint32_t* aggsh = (uint32_t*)(smem + FB_FLOATS);         // [16 warps][16 Mrows][20 w]
    float*    sWf   = (float*)(aggsh + AG_WORDS);            // [CINV][COUTV]

    const int tid   = threadIdx.x;
    const int lane  = tid & 31;
    const int warp  = tid >> 5;          // 0..15
    const int ho    = lane >> 4;         // which o of the warp's pair (phase 1)
    const int hl    = lane & 15;         // channel-pair index (phase 1)
    const int obase = blockIdx.y * 32;   // this block's o-half
    const int ogl   = warp * 2 + ho;     // phase-1 local o

    for (int i = tid; i < WF_FLOATS; i += NTH) sWf[i] = Wf[i];
    __syncthreads();

    // Persistent B fragments (Wf as fp16, col n = lane/4, k = (lane%4)*2 base)
    // and bias pairs for D init. mma.m16n8k16 B layout.
    uint32_t Bf[4][2][2];
    float2 biasf[4];
    {
        int nq = lane >> 2, kq = (lane & 3) * 2;
        #pragma unroll
        for (int nt = 0; nt < 4; nt++) {
            int n = nt * 8 + nq;
            #pragma unroll
            for (int kt = 0; kt < 2; kt++) {
                int k0 = kt * 16 + kq;
                __half2 b0 = __floats2half2_rn(sWf[k0 * COUTV + n],       sWf[(k0 + 1) * COUTV + n]);
                __half2 b1 = __floats2half2_rn(sWf[(k0 + 8) * COUTV + n], sWf[(k0 + 9) * COUTV + n]);
                Bf[nt][kt][0] = *(uint32_t*)&b0;
                Bf[nt][kt][1] = *(uint32_t*)&b1;
            }
            biasf[nt].x = bias_out[nt * 8 + kq];
            biasf[nt].y = bias_out[nt * 8 + kq + 1];
        }
    }

    // ldmatrix source addresses for this warp's A tile (x4: m = lane&15, chunk = lane>>4)
    uint32_t a_base;
    {
        char* ap = (char*)(aggsh + warp * (16 * AG_STRIDE_W)) + (lane & 15) * 80 + (lane >> 4) * 16;
        a_base = (uint32_t)__cvta_generic_to_shared(ap);
    }
    uint32_t* awarp = aggsh + warp * (16 * AG_STRIDE_W);

    long long R = (long long)B * N;
    long long chunk = (R + gridDim.x - 1) / gridDim.x;
    long long r0 = (long long)blockIdx.x * chunk;
    long long r1 = r0 + chunk; if (r1 > R) r1 = R;
    if (r0 >= r1) return;

    ull      Mp[16];
    uint32_t ip[8];

    long long g = r0;
    while (g < r1) {
        int b = (int)(g / N);
        long long gend = (long long)(b + 1) * N; if (gend > r1) gend = r1;

        // Per-batch tables: weights as native float2 (per-channel pair), u16 offsets.
        {
            int og = obase + ogl;
            const ull* mp = (const ull*)(g_Mw + (size_t)(b * OPAD + og) * KMAX * CINV);
            #pragma unroll
            for (int k = 0; k < 16; k++) Mp[k] = mp[k * (CINV / 2) + hl];
            const uint32_t* q = (const uint32_t*)&g_selo[(b * OPAD + og) * KMAX];
            #pragma unroll
            for (int j = 0; j < 8; j++) ip[j] = q[j];
        }

        {
            int nfirst = (int)((gend - g) < NRB ? (gend - g) : NRB);
            async_rows(fbuf, f_in + g * ROWF, nfirst, tid);
        }

        int pb = 0;
        for (long long t = g; t < gend; t += NRB, pb ^= 1) {
            long long tn = t + NRB;
            if (tn < gend) {
                int nr = (int)((gend - tn) < NRB ? (gend - tn) : NRB);
                async_rows(fbuf + (pb ^ 1) * (NRB * ROWF), f_in + tn * ROWF, nr, tid);
                asm volatile("cp.async.wait_group 1;\n" ::: "memory");
            } else {
                asm volatile("cp.async.wait_group 0;\n" ::: "memory");
            }
            __syncthreads();   // batch ready

            const int nrows = (int)((gend - t) < NRB ? (gend - t) : NRB);

            phase1((const char*)(fbuf + pb * (NRB * ROWF)), awarp, Mp, ip, ho, hl);

            // REQUIRED block barrier: fbuf[pb] readers done before refill; also
            // makes this warp's A-tile stores visible for ldmatrix below.
            __syncthreads();

            // ---- Phase 2: HMMA. A = warp's 16x32 fp16 tile, B = Wf frags. ----
            uint32_t a0[4], a1[4];
            asm volatile("ldmatrix.sync.aligned.m8n8.x4.shared.b16 {%0,%1,%2,%3}, [%4];"
                         : "=r"(a0[0]), "=r"(a0[1]), "=r"(a0[2]), "=r"(a0[3]) : "r"(a_base));
            asm volatile("ldmatrix.sync.aligned.m8n8.x4.shared.b16 {%0,%1,%2,%3}, [%4];"
                         : "=r"(a1[0]), "=r"(a1[1]), "=r"(a1[2]), "=r"(a1[3]) : "r"(a_base + 32));

            const int gr   = lane >> 2;            // row r (0..7) for both m-halves
            const int ncol = (lane & 3) * 2;
            const int og0  = obase + warp * 2;
            const int og1  = og0 + 1;
            const bool dostore = (gr < nrows);
            float* rowp = out + (t + gr) * (QOUT * COUTV);

            #pragma unroll
            for (int nt = 0; nt < 4; nt++) {
                float d0 = biasf[nt].x, d1 = biasf[nt].y, d2 = biasf[nt].x, d3 = biasf[nt].y;
                asm volatile("mma.sync.aligned.m16n8k16.row.col.f32.f16.f16.f32 "
                             "{%0,%1,%2,%3}, {%4,%5,%6,%7}, {%8,%9}, {%0,%1,%2,%3};"
                             : "+f"(d0), "+f"(d1), "+f"(d2), "+f"(d3)
                             : "r"(a0[0]), "r"(a0[1]), "r"(a0[2]), "r"(a0[3]),
                               "r"(Bf[nt][0][0]), "r"(Bf[nt][0][1]));
                asm volatile("mma.sync.aligned.m16n8k16.row.col.f32.f16.f16.f32 "
                             "{%0,%1,%2,%3}, {%4,%5,%6,%7}, {%8,%9}, {%0,%1,%2,%3};"
                             : "+f"(d0), "+f"(d1), "+f"(d2), "+f"(d3)
                             : "r"(a1[0]), "r"(a1[1]), "r"(a1[2]), "r"(a1[3]),
                               "r"(Bf[nt][1][0]), "r"(Bf[nt][1][1]));
                if (dostore) {
                    if (og0 < QOUT) {
                        float2 v; v.x = d0; v.y = d1;
                        *(float2*)(rowp + og0 * COUTV + nt * 8 + ncol) = v;
                    }
                    if (og1 < QOUT) {
                        float2 v; v.x = d2; v.y = d3;
                        *(float2*)(rowp + og1 * COUTV + nt * 8 + ncol) = v;
                    }
                }
            }
        }
        g = gend;
    }
}

// ---------------------------------------------------------------------------
extern "C" void kernel_launch(void* const* d_in, const int* in_sizes, int n_in,
                              void* d_out, int out_size)
{
    const float* ang_in   = (const float*)d_in[0];
    const float* ang_out  = (const float*)d_in[1];
    const float* f_in     = (const float*)d_in[2];
    const float* W1       = (const float*)d_in[3];
    const float* b1       = (const float*)d_in[4];
    const float* W2       = (const float*)d_in[5];
    const float* b2       = (const float*)d_in[6];
    const float* W3       = (const float*)d_in[7];
    const float* b3       = (const float*)d_in[8];
    const float* Wf       = (const float*)d_in[9];
    const float* bias_out = (const float*)d_in[10];
    float* out = (float*)d_out;

    int B = in_sizes[0] / (QIN * 3);
    int N = in_sizes[2] / (B * QIN * CINV);

    cudaFuncSetAttribute(conv_kernel, cudaFuncAttributeMaxDynamicSharedMemorySize, SMEM_BYTES);

    prep_kernel<<<B * OPAD, 128>>>(ang_in, ang_out, W1, b1, W2, b2, W3, b3, B);

    int nsm = 148;
    cudaDeviceGetAttribute(&nsm, cudaDevAttrMultiProcessorCount, 0);
    int gx = nsm / 2; if (gx < 1) gx = 1;   // (gx, 2) = nsm blocks -> one wave
    dim3 grid(gx, 2);
    conv_kernel<<<grid, NTH, SMEM_BYTES>>>(f_in, Wf, bias_out, out, B, N);
}

// round 16
// speedup vs baseline: 1.8408x; 1.0644x over previous
#include <cuda_runtime.h>
#include <cuda_fp16.h>
#include <stdint.h>

#define QIN   90
#define QOUT  60
#define OPAD  64
#define KMAX  16
#define CINV  32
#define COUTV 32
#define H1V   32
#define H2V   64
#define DMAXV 1.0f
#define MAXB  4
#define ROWF  (QIN * CINV)   // 2880 floats per (b,n) row
#define ROWB  (ROWF * 4)     // 11520 bytes
#define NRB   8              // rows per batch
#define NTH   512
#define FB_FLOATS (2 * NRB * ROWF)              // 46080 floats = 184320 B
#define AG_STRIDE_W 20                          // 80 B per M-row (conflict-free LDSM)
#define AG_WORDS  (16 * 16 * AG_STRIDE_W)       // 5120 words
#define WF_FLOATS (CINV * COUTV)                // 1024
// fbuf | A-tiles | sWf | mbarriers (4 x u64)
#define SMEM_BYTES (FB_FLOATS * 4 + AG_WORDS * 4 + WF_FLOATS * 4 + 32)

typedef unsigned long long ull;
typedef long long ll;
#define FFMA2(acc, a, b) \
    asm("fma.rn.f32x2 %0, %1, %2, %0;" : "+l"(acc) : "l"(a), "l"(b))

// Per-(b,o) compacted tables produced by prep_kernel.
__device__ float          g_Mw[MAXB * OPAD * KMAX * CINV];  // [b][o][k][c], masked weights
__device__ unsigned short g_selo[MAXB * OPAD * KMAX];       // [b][o][k], BYTE offset i*128

// ---------------------------------------------------------------------------
// Kernel 1: distances + top-K selection + WeightNet MLP -> compact tables
// ---------------------------------------------------------------------------
__global__ void prep_kernel(const float* __restrict__ ang_in, const float* __restrict__ ang_out,
                            const float* __restrict__ W1, const float* __restrict__ b1,
                            const float* __restrict__ W2, const float* __restrict__ b2,
                            const float* __restrict__ W3, const float* __restrict__ b3,
                            int B)
{
    int bo = blockIdx.x;
    int b = bo / OPAD, o = bo % OPAD;
    int tid = threadIdx.x;

    if (o >= QOUT) {
        for (int i = tid; i < KMAX * CINV; i += blockDim.x)
            g_Mw[(b * OPAD + o) * KMAX * CINV + i] = 0.f;
        if (tid < KMAX) g_selo[(b * OPAD + o) * KMAX + tid] = 0;
        return;
    }

    __shared__ float sd[QIN], sbd[QIN];
    __shared__ int   ssel[KMAX];
    __shared__ float smask[KMAX], skd[KMAX], skbd[KMAX];
    __shared__ float sW2[H1V * H2V], sW3[H2V * CINV];
    __shared__ float sW1a[H1V], sW1b[H1V], sb1[H1V], sb2[H2V], sb3[CINV];
    __shared__ float sh1[KMAX][H1V], sh2[KMAX][H2V];

    for (int i = tid; i < H1V * H2V; i += 128) sW2[i] = W2[i];
    for (int i = tid; i < H2V * CINV; i += 128) sW3[i] = W3[i];
    if (tid < H2V) sb2[tid] = b2[tid];
    if (tid < CINV) sb3[tid] = b3[tid];
    if (tid < H1V) { sW1a[tid] = W1[3 * H1V + tid]; sW1b[tid] = W1[4 * H1V + tid]; sb1[tid] = b1[tid]; }

    float aox = ang_out[(b * QOUT + o) * 3 + 0];
    float aoy = ang_out[(b * QOUT + o) * 3 + 1];
    float aoz = ang_out[(b * QOUT + o) * 3 + 2];
    float nout = sqrtf(aox * aox + aoy * aoy + aoz * aoz);
    float ivo = (nout > 0.f) ? 1.f / nout : 0.f;
    float uox = aox * ivo, uoy = aoy * ivo, uoz = aoz * ivo;

    if (tid < QIN) {
        float x = ang_in[(b * QIN + tid) * 3 + 0];
        float y = ang_in[(b * QIN + tid) * 3 + 1];
        float z = ang_in[(b * QIN + tid) * 3 + 2];
        float nin = sqrtf(x * x + y * y + z * z);
        float ivi = (nin > 0.f) ? 1.f / nin : 0.f;
        float dot = (x * ivi) * uox + (y * ivi) * uoy + (z * ivi) * uoz;
        float d = acosf(fminf(fabsf(dot), 1.0f - 1e-7f));
        sd[tid] = d;
        sbd[tid] = nout - nin;
    }
    __syncthreads();

    if (tid < QIN) {
        float dt = sd[tid];
        int r = 0;
        for (int j = 0; j < QIN; j++) {
            float dj = sd[j];
            r += (dj < dt || (dj == dt && j < tid)) ? 1 : 0;
        }
        if (r < KMAX) {
            ssel[r] = tid;
            smask[r] = (dt <= DMAXV) ? 1.f : 0.f;
            skd[r] = dt;
            skbd[r] = sbd[tid];
        }
    }
    __syncthreads();

    int k = tid >> 3, ln = tid & 7;
    {
        float d = skd[k], bd = skbd[k];
        #pragma unroll
        for (int jj = 0; jj < 4; jj++) {
            int j = ln * 4 + jj;
            float h = fmaf(d, sW1a[j], fmaf(bd, sW1b[j], sb1[j]));
            sh1[k][j] = fmaxf(h, 0.f);
        }
    }
    __syncthreads();
    #pragma unroll
    for (int ll2 = 0; ll2 < 8; ll2++) {
        int l = ln * 8 + ll2;
        float acc = sb2[l];
        #pragma unroll 8
        for (int j = 0; j < H1V; j++) acc = fmaf(sh1[k][j], sW2[j * H2V + l], acc);
        sh2[k][l] = fmaxf(acc, 0.f);
    }
    __syncthreads();
    float m = smask[k];
    #pragma unroll
    for (int cc = 0; cc < 4; cc++) {
        int c = ln * 4 + cc;
        float acc = sb3[c];
        #pragma unroll 8
        for (int l = 0; l < H2V; l++) acc = fmaf(sh2[k][l], sW3[l * CINV + c], acc);
        g_Mw[((b * OPAD + o) * KMAX + k) * CINV + c] = m * acc;
    }
    if (ln == 0) g_selo[(b * OPAD + o) * KMAX + k] = (unsigned short)(ssel[k] * 128);
}

// ---------------------------------------------------------------------------
// mbarrier helpers
// ---------------------------------------------------------------------------
__device__ __forceinline__ void mbar_init(uint32_t a, uint32_t cnt) {
    asm volatile("mbarrier.init.shared.b64 [%0], %1;" :: "r"(a), "r"(cnt) : "memory");
}
__device__ __forceinline__ void mbar_arrive(uint32_t a) {
    asm volatile("mbarrier.arrive.shared.b64 _, [%0];" :: "r"(a) : "memory");
}
__device__ __forceinline__ void mbar_expect_tx(uint32_t a, uint32_t bytes) {
    asm volatile("mbarrier.arrive.expect_tx.shared.b64 _, [%0], %1;" :: "r"(a), "r"(bytes) : "memory");
}
__device__ __forceinline__ void mbar_wait(uint32_t a, uint32_t parity) {
    asm volatile(
        "{\n\t.reg .pred P;\n\t"
        "W%=:\n\t"
        "mbarrier.try_wait.parity.acquire.cta.shared::cta.b64 P, [%0], %1, 0x989680;\n\t"
        "@!P bra W%=;\n\t}"
        :: "r"(a), "r"(parity) : "memory");
}
__device__ __forceinline__ void tma_bulk(uint32_t dst, const void* src, uint32_t bytes, uint32_t mbar) {
    asm volatile("cp.async.bulk.shared::cta.global.mbarrier::complete_tx::bytes [%0], [%1], %2, [%3];"
                 :: "r"(dst), "l"(src), "r"(bytes), "r"(mbar) : "memory");
}

// Phase 1: gather-reduce (champion), result -> fp16 A-tile (own warp region).
__device__ __forceinline__ void phase1(const char* __restrict__ fbc, uint32_t* __restrict__ atile,
                                       const ull (&Mp)[16], const uint32_t (&ip)[8],
                                       int ho, int hl)
{
    ull acc[NRB];
    #pragma unroll
    for (int r = 0; r < NRB; r++) acc[r] = 0ULL;

    #pragma unroll
    for (int k = 0; k < 16; k++) {
        int off = (int)((ip[k >> 1] >> ((k & 1) * 16)) & 0xFFFFu);
        const char* p = fbc + off + hl * 8;
        ull m = Mp[k];
        #pragma unroll
        for (int r = 0; r < NRB; r++) {
            ull v = *(const ull*)(p + r * ROWB);   // LDS.64
            FFMA2(acc[r], m, v);
        }
    }
    #pragma unroll
    for (int r = 0; r < NRB; r++) {
        float lo = __uint_as_float((uint32_t)acc[r]);
        float hi = __uint_as_float((uint32_t)(acc[r] >> 32));
        __half2 h = __floats2half2_rn(lo, hi);
        atile[(ho * 8 + r) * AG_STRIDE_W + hl] = *(uint32_t*)&h;   // STS.32
    }
}

// next batch start after s (batches NRB-strided within each b-segment)
__device__ __forceinline__ ll nextb(ll s, ll r1, int N) {
    ll segend = ((s / N) + 1) * (ll)N;
    if (segend > r1) segend = r1;
    ll n = s + NRB;
    return n < segend ? n : segend;
}

__global__ void __launch_bounds__(NTH, 1)
conv_kernel(const float* __restrict__ f_in, const float* __restrict__ Wf,
            const float* __restrict__ bias_out, float* __restrict__ out,
            int B, int N)
{
    extern __shared__ float smem[];
    float*    fbuf  = smem;                                  // [2][NRB * ROWF]
    uint32_t* aggsh = (uint32_t*)(smem + FB_FLOATS);         // A tiles
    float*    sWf   = (float*)(aggsh + AG_WORDS);            // [CINV][COUTV]
    uint32_t  mb_base = (uint32_t)__cvta_generic_to_shared(sWf + WF_FLOATS);
    // mbarriers: full[0]@+0, full[1]@+8, empty[0]@+16, empty[1]@+24
    uint32_t  fbuf_sa = (uint32_t)__cvta_generic_to_shared(fbuf);

    const int tid   = threadIdx.x;
    const int lane  = tid & 31;
    const int warp  = tid >> 5;          // 0..15
    const int ho    = lane >> 4;
    const int hl    = lane & 15;
    const int obase = blockIdx.y * 32;
    const int ogl   = warp * 2 + ho;

    for (int i = tid; i < WF_FLOATS; i += NTH) sWf[i] = Wf[i];
    if (tid == 0) {
        mbar_init(mb_base + 0, 1);    // full[0] (expect_tx arms tx count)
        mbar_init(mb_base + 8, 1);    // full[1]
        mbar_init(mb_base + 16, 16);  // empty[0]: 16 warps
        mbar_init(mb_base + 24, 16);  // empty[1]
    }
    __syncthreads();

    // Persistent B fragments (Wf fp16) + bias (mma.m16n8k16 layouts)
    uint32_t Bf[4][2][2];
    float2 biasf[4];
    {
        int nq = lane >> 2, kq = (lane & 3) * 2;
        #pragma unroll
        for (int nt = 0; nt < 4; nt++) {
            int n = nt * 8 + nq;
            #pragma unroll
            for (int kt = 0; kt < 2; kt++) {
                int k0 = kt * 16 + kq;
                __half2 b0 = __floats2half2_rn(sWf[k0 * COUTV + n],       sWf[(k0 + 1) * COUTV + n]);
                __half2 b1 = __floats2half2_rn(sWf[(k0 + 8) * COUTV + n], sWf[(k0 + 9) * COUTV + n]);
                Bf[nt][kt][0] = *(uint32_t*)&b0;
                Bf[nt][kt][1] = *(uint32_t*)&b1;
            }
            biasf[nt].x = bias_out[nt * 8 + kq];
            biasf[nt].y = bias_out[nt * 8 + kq + 1];
        }
    }

    uint32_t a_base;
    {
        char* ap = (char*)(aggsh + warp * (16 * AG_STRIDE_W)) + (lane & 15) * 80 + (lane >> 4) * 16;
        a_base = (uint32_t)__cvta_generic_to_shared(ap);
    }
    uint32_t* awarp = aggsh + warp * (16 * AG_STRIDE_W);

    long long R = (long long)B * N;
    long long chunk = (R + gridDim.x - 1) / gridDim.x;
    long long r0 = (long long)blockIdx.x * chunk;
    long long r1 = r0 + chunk; if (r1 > R) r1 = R;
    if (r0 >= r1) return;   // uniform across block for this grid

    // Prologue: producer (tid 0) issues batches 0 and 1.
    ll s1 = nextb(r0, r1, N);
    if (tid == 0) {
        {
            ll se = ((r0 / N) + 1) * (ll)N; if (se > r1) se = r1;
            uint32_t bytes = (uint32_t)((se - r0 < NRB ? se - r0 : NRB) * ROWB);
            mbar_expect_tx(mb_base + 0, bytes);
            tma_bulk(fbuf_sa, f_in + r0 * ROWF, bytes, mb_base + 0);
        }
        if (s1 < r1) {
            ll se = ((s1 / N) + 1) * (ll)N; if (se > r1) se = r1;
            uint32_t bytes = (uint32_t)((se - s1 < NRB ? se - s1 : NRB) * ROWB);
            mbar_expect_tx(mb_base + 8, bytes);
            tma_bulk(fbuf_sa + NRB * ROWB, f_in + s1 * ROWF, bytes, mb_base + 8);
        }
    }
    ll s_ahead = (s1 < r1) ? nextb(s1, r1, N) : r1;

    ull      Mp[16];
    uint32_t ip[8];
    int bcur = -1;
    uint32_t fpar = 0, epar = 0;   // per-buffer phase bits (bit pb)

    ll s = r0;
    int bi = 0;
    while (s < r1) {
        ll segend = ((s / N) + 1) * (ll)N; if (segend > r1) segend = r1;
        int b = (int)(s / N);
        if (b != bcur) {
            bcur = b;
            int og = obase + ogl;
            const ull* mp = (const ull*)(g_Mw + (size_t)(b * OPAD + og) * KMAX * CINV);
            #pragma unroll
            for (int k = 0; k < 16; k++) Mp[k] = mp[k * (CINV / 2) + hl];
            const uint32_t* q = (const uint32_t*)&g_selo[(b * OPAD + og) * KMAX];
            #pragma unroll
            for (int j = 0; j < 8; j++) ip[j] = q[j];
        }
        const int nrows = (int)((segend - s) < NRB ? (segend - s) : NRB);
        const int pb = bi & 1;

        // Consume: wait batch data (acquire)
        mbar_wait(mb_base + pb * 8, (fpar >> pb) & 1);

        phase1((const char*)(fbuf + pb * (NRB * ROWF)), awarp, Mp, ip, ho, hl);
        __syncwarp();
        if (lane == 0) mbar_arrive(mb_base + 16 + pb * 8);   // release: fbuf reads done

        // Producer: refill this buffer for batch bi+2 once all 16 warps emptied it.
        if (tid == 0 && s_ahead < r1) {
            mbar_wait(mb_base + 16 + pb * 8, (epar >> pb) & 1);
            epar ^= (1u << pb);
            ll se2 = ((s_ahead / N) + 1) * (ll)N; if (se2 > r1) se2 = r1;
            uint32_t bytes = (uint32_t)((se2 - s_ahead < NRB ? se2 - s_ahead : NRB) * ROWB);
            mbar_expect_tx(mb_base + pb * 8, bytes);
            tma_bulk(fbuf_sa + pb * (NRB * ROWB), f_in + s_ahead * ROWF, bytes, mb_base + pb * 8);
            s_ahead = nextb(s_ahead, r1, N);
        }
        fpar ^= (1u << pb);

        // ---- Phase 2: HMMA on own A-tile (no block sync needed) ----
        uint32_t a0[4], a1[4];
        asm volatile("ldmatrix.sync.aligned.m8n8.x4.shared.b16 {%0,%1,%2,%3}, [%4];"
                     : "=r"(a0[0]), "=r"(a0[1]), "=r"(a0[2]), "=r"(a0[3]) : "r"(a_base));
        asm volatile("ldmatrix.sync.aligned.m8n8.x4.shared.b16 {%0,%1,%2,%3}, [%4];"
                     : "=r"(a1[0]), "=r"(a1[1]), "=r"(a1[2]), "=r"(a1[3]) : "r"(a_base + 32));

        const int gr   = lane >> 2;
        const int ncol = (lane & 3) * 2;
        const int og0  = obase + warp * 2;
        const int og1  = og0 + 1;
        const bool dostore = (gr < nrows);
        float* rowp = out + (s + gr) * (QOUT * COUTV);

        #pragma unroll
        for (int nt = 0; nt < 4; nt++) {
            float d0 = biasf[nt].x, d1 = biasf[nt].y, d2 = biasf[nt].x, d3 = biasf[nt].y;
            asm volatile("mma.sync.aligned.m16n8k16.row.col.f32.f16.f16.f32 "
                         "{%0,%1,%2,%3}, {%4,%5,%6,%7}, {%8,%9}, {%0,%1,%2,%3};"
                         : "+f"(d0), "+f"(d1), "+f"(d2), "+f"(d3)
                         : "r"(a0[0]), "r"(a0[1]), "r"(a0[2]), "r"(a0[3]),
                           "r"(Bf[nt][0][0]), "r"(Bf[nt][0][1]));
            asm volatile("mma.sync.aligned.m16n8k16.row.col.f32.f16.f16.f32 "
                         "{%0,%1,%2,%3}, {%4,%5,%6,%7}, {%8,%9}, {%0,%1,%2,%3};"
                         : "+f"(d0), "+f"(d1), "+f"(d2), "+f"(d3)
                         : "r"(a1[0]), "r"(a1[1]), "r"(a1[2]), "r"(a1[3]),
                           "r"(Bf[nt][1][0]), "r"(Bf[nt][1][1]));
            if (dostore) {
                if (og0 < QOUT) {
                    float2 v; v.x = d0; v.y = d1;
                    *(float2*)(rowp + og0 * COUTV + nt * 8 + ncol) = v;
                }
                if (og1 < QOUT) {
                    float2 v; v.x = d2; v.y = d3;
                    *(float2*)(rowp + og1 * COUTV + nt * 8 + ncol) = v;
                }
            }
        }

        s = nextb(s, r1, N);
        bi++;
    }
}

// ---------------------------------------------------------------------------
extern "C" void kernel_launch(void* const* d_in, const int* in_sizes, int n_in,
                              void* d_out, int out_size)
{
    const float* ang_in   = (const float*)d_in[0];
    const float* ang_out  = (const float*)d_in[1];
    const float* f_in     = (const float*)d_in[2];
    const float* W1       = (const float*)d_in[3];
    const float* b1       = (const float*)d_in[4];
    const float* W2       = (const float*)d_in[5];
    const float* b2       = (const float*)d_in[6];
    const float* W3       = (const float*)d_in[7];
    const float* b3       = (const float*)d_in[8];
    const float* Wf       = (const float*)d_in[9];
    const float* bias_out = (const float*)d_in[10];
    float* out = (float*)d_out;

    int B = in_sizes[0] / (QIN * 3);
    int N = in_sizes[2] / (B * QIN * CINV);

    cudaFuncSetAttribute(conv_kernel, cudaFuncAttributeMaxDynamicSharedMemorySize, SMEM_BYTES);

    prep_kernel<<<B * OPAD, 128>>>(ang_in, ang_out, W1, b1, W2, b2, W3, b3, B);

    int nsm = 148;
    cudaDeviceGetAttribute(&nsm, cudaDevAttrMultiProcessorCount, 0);
    int gx = nsm / 2; if (gx < 1) gx = 1;   // (gx, 2) = nsm blocks -> one wave
    dim3 grid(gx, 2);
    conv_kernel<<<grid, NTH, SMEM_BYTES>>>(f_in, Wf, bias_out, out, B, N);
}

// round 17
// speedup vs baseline: 1.9443x; 1.0562x over previous
#include <cuda_runtime.h>
#include <cuda_fp16.h>
#include <stdint.h>

#define QIN   90
#define QOUT  60
#define OPAD  64
#define KMAX  16
#define CINV  32
#define COUTV 32
#define H1V   32
#define H2V   64
#define DMAXV 1.0f
#define MAXB  4
#define ROWF  (QIN * CINV)   // 2880 floats per (b,n) row
#define ROWB  (ROWF * 4)     // 11520 bytes
#define NRB   4              // rows per batch
#define NBUF  4              // ring depth
#define NTH   512
#define FB_FLOATS (NBUF * NRB * ROWF)           // 46080 floats = 184320 B
#define AG_STRIDE_W 20                          // 80 B per M-row (conflict-free LDSM)
#define AG_WORDS  (16 * 8 * AG_STRIDE_W)        // 2560 words = 10240 B
#define WF_FLOATS (CINV * COUTV)                // 1024
#define SMEM_BYTES (FB_FLOATS * 4 + AG_WORDS * 4 + WF_FLOATS * 4 + 64)

typedef unsigned long long ull;
typedef long long ll;
#define FFMA2(acc, a, b) \
    asm("fma.rn.f32x2 %0, %1, %2, %0;" : "+l"(acc) : "l"(a), "l"(b))

__device__ float          g_Mw[MAXB * OPAD * KMAX * CINV];
__device__ unsigned short g_selo[MAXB * OPAD * KMAX];

// ---------------------------------------------------------------------------
__global__ void prep_kernel(const float* __restrict__ ang_in, const float* __restrict__ ang_out,
                            const float* __restrict__ W1, const float* __restrict__ b1,
                            const float* __restrict__ W2, const float* __restrict__ b2,
                            const float* __restrict__ W3, const float* __restrict__ b3,
                            int B)
{
    int bo = blockIdx.x;
    int b = bo / OPAD, o = bo % OPAD;
    int tid = threadIdx.x;

    if (o >= QOUT) {
        for (int i = tid; i < KMAX * CINV; i += blockDim.x)
            g_Mw[(b * OPAD + o) * KMAX * CINV + i] = 0.f;
        if (tid < KMAX) g_selo[(b * OPAD + o) * KMAX + tid] = 0;
        return;
    }

    __shared__ float sd[QIN], sbd[QIN];
    __shared__ int   ssel[KMAX];
    __shared__ float smask[KMAX], skd[KMAX], skbd[KMAX];
    __shared__ float sW2[H1V * H2V], sW3[H2V * CINV];
    __shared__ float sW1a[H1V], sW1b[H1V], sb1[H1V], sb2[H2V], sb3[CINV];
    __shared__ float sh1[KMAX][H1V], sh2[KMAX][H2V];

    for (int i = tid; i < H1V * H2V; i += 128) sW2[i] = W2[i];
    for (int i = tid; i < H2V * CINV; i += 128) sW3[i] = W3[i];
    if (tid < H2V) sb2[tid] = b2[tid];
    if (tid < CINV) sb3[tid] = b3[tid];
    if (tid < H1V) { sW1a[tid] = W1[3 * H1V + tid]; sW1b[tid] = W1[4 * H1V + tid]; sb1[tid] = b1[tid]; }

    float aox = ang_out[(b * QOUT + o) * 3 + 0];
    float aoy = ang_out[(b * QOUT + o) * 3 + 1];
    float aoz = ang_out[(b * QOUT + o) * 3 + 2];
    float nout = sqrtf(aox * aox + aoy * aoy + aoz * aoz);
    float ivo = (nout > 0.f) ? 1.f / nout : 0.f;
    float uox = aox * ivo, uoy = aoy * ivo, uoz = aoz * ivo;

    if (tid < QIN) {
        float x = ang_in[(b * QIN + tid) * 3 + 0];
        float y = ang_in[(b * QIN + tid) * 3 + 1];
        float z = ang_in[(b * QIN + tid) * 3 + 2];
        float nin = sqrtf(x * x + y * y + z * z);
        float ivi = (nin > 0.f) ? 1.f / nin : 0.f;
        float dot = (x * ivi) * uox + (y * ivi) * uoy + (z * ivi) * uoz;
        float d = acosf(fminf(fabsf(dot), 1.0f - 1e-7f));
        sd[tid] = d;
        sbd[tid] = nout - nin;
    }
    __syncthreads();

    if (tid < QIN) {
        float dt = sd[tid];
        int r = 0;
        for (int j = 0; j < QIN; j++) {
            float dj = sd[j];
            r += (dj < dt || (dj == dt && j < tid)) ? 1 : 0;
        }
        if (r < KMAX) {
            ssel[r] = tid;
            smask[r] = (dt <= DMAXV) ? 1.f : 0.f;
            skd[r] = dt;
            skbd[r] = sbd[tid];
        }
    }
    __syncthreads();

    int k = tid >> 3, ln = tid & 7;
    {
        float d = skd[k], bd = skbd[k];
        #pragma unroll
        for (int jj = 0; jj < 4; jj++) {
            int j = ln * 4 + jj;
            float h = fmaf(d, sW1a[j], fmaf(bd, sW1b[j], sb1[j]));
            sh1[k][j] = fmaxf(h, 0.f);
        }
    }
    __syncthreads();
    #pragma unroll
    for (int ll2 = 0; ll2 < 8; ll2++) {
        int l = ln * 8 + ll2;
        float acc = sb2[l];
        #pragma unroll 8
        for (int j = 0; j < H1V; j++) acc = fmaf(sh1[k][j], sW2[j * H2V + l], acc);
        sh2[k][l] = fmaxf(acc, 0.f);
    }
    __syncthreads();
    float m = smask[k];
    #pragma unroll
    for (int cc = 0; cc < 4; cc++) {
        int c = ln * 4 + cc;
        float acc = sb3[c];
        #pragma unroll 8
        for (int l = 0; l < H2V; l++) acc = fmaf(sh2[k][l], sW3[l * CINV + c], acc);
        g_Mw[((b * OPAD + o) * KMAX + k) * CINV + c] = m * acc;
    }
    if (ln == 0) g_selo[(b * OPAD + o) * KMAX + k] = (unsigned short)(ssel[k] * 128);
}

// ---------------------------------------------------------------------------
__device__ __forceinline__ void mbar_init(uint32_t a, uint32_t cnt) {
    asm volatile("mbarrier.init.shared.b64 [%0], %1;" :: "r"(a), "r"(cnt) : "memory");
}
__device__ __forceinline__ void mbar_arrive(uint32_t a) {
    asm volatile("mbarrier.arrive.shared.b64 _, [%0];" :: "r"(a) : "memory");
}
__device__ __forceinline__ void mbar_expect_tx(uint32_t a, uint32_t bytes) {
    asm volatile("mbarrier.arrive.expect_tx.shared.b64 _, [%0], %1;" :: "r"(a), "r"(bytes) : "memory");
}
__device__ __forceinline__ void mbar_wait(uint32_t a, uint32_t parity) {
    asm volatile(
        "{\n\t.reg .pred P;\n\t"
        "W%=:\n\t"
        "mbarrier.try_wait.parity.acquire.cta.shared::cta.b64 P, [%0], %1, 0x989680;\n\t"
        "@!P bra W%=;\n\t}"
        :: "r"(a), "r"(parity) : "memory");
}
__device__ __forceinline__ void tma_bulk(uint32_t dst, const void* src, uint32_t bytes, uint32_t mbar) {
    asm volatile("cp.async.bulk.shared::cta.global.mbarrier::complete_tx::bytes [%0], [%1], %2, [%3];"
                 :: "r"(dst), "l"(src), "r"(bytes), "r"(mbar) : "memory");
}

// Phase 1: champion gather; NRB=4 rows -> fp16 A-tile rows (ho*4 + r).
__device__ __forceinline__ void phase1(const char* __restrict__ fbc, uint32_t* __restrict__ atile,
                                       const ull (&Mp)[16], const uint32_t (&ip)[8],
                                       int ho, int hl)
{
    ull acc[NRB];
    #pragma unroll
    for (int r = 0; r < NRB; r++) acc[r] = 0ULL;

    #pragma unroll
    for (int k = 0; k < 16; k++) {
        int off = (int)((ip[k >> 1] >> ((k & 1) * 16)) & 0xFFFFu);
        const char* p = fbc + off + hl * 8;
        ull m = Mp[k];
        #pragma unroll
        for (int r = 0; r < NRB; r++) {
            ull v = *(const ull*)(p + r * ROWB);   // LDS.64
            FFMA2(acc[r], m, v);
        }
    }
    #pragma unroll
    for (int r = 0; r < NRB; r++) {
        float lo = __uint_as_float((uint32_t)acc[r]);
        float hi = __uint_as_float((uint32_t)(acc[r] >> 32));
        __half2 h = __floats2half2_rn(lo, hi);
        atile[(ho * 4 + r) * AG_STRIDE_W + hl] = *(uint32_t*)&h;   // STS.32
    }
}

__device__ __forceinline__ ll nextb(ll s, ll r1, int N) {
    ll segend = ((s / N) + 1) * (ll)N;
    if (segend > r1) segend = r1;
    ll n = s + NRB;
    return n < segend ? n : segend;
}

__global__ void __launch_bounds__(NTH, 1)
conv_kernel(const float* __restrict__ f_in, const float* __restrict__ Wf,
            const float* __restrict__ bias_out, float* __restrict__ out,
            int B, int N)
{
    extern __shared__ float smem[];
    float*    fbuf  = smem;                                  // [NBUF][NRB * ROWF]
    uint32_t* aggsh = (uint32_t*)(smem + FB_FLOATS);         // A tiles (8 rows/warp)
    float*    sWf   = (float*)(aggsh + AG_WORDS);            // [CINV][COUTV]
    uint32_t  mb_base = (uint32_t)__cvta_generic_to_shared(sWf + WF_FLOATS);
    uint32_t  fbuf_sa = (uint32_t)__cvta_generic_to_shared(fbuf);

    const int tid   = threadIdx.x;
    const int lane  = tid & 31;
    const int warp  = tid >> 5;
    const int ho    = lane >> 4;
    const int hl    = lane & 15;
    const int obase = blockIdx.y * 32;
    const int ogl   = warp * 2 + ho;

    for (int i = tid; i < WF_FLOATS; i += NTH) sWf[i] = Wf[i];
    if (tid == 0) {
        #pragma unroll
        for (int i = 0; i < NBUF; i++) {
            mbar_init(mb_base + i * 8, 1);         // full[i]
            mbar_init(mb_base + 32 + i * 8, 16);   // empty[i]
        }
    }
    __syncthreads();

    // Persistent B fragments (Wf fp16) + bias
    uint32_t Bf[4][2][2];
    float2 biasf[4];
    {
        int nq = lane >> 2, kq = (lane & 3) * 2;
        #pragma unroll
        for (int nt = 0; nt < 4; nt++) {
            int n = nt * 8 + nq;
            #pragma unroll
            for (int kt = 0; kt < 2; kt++) {
                int k0 = kt * 16 + kq;
                __half2 b0 = __floats2half2_rn(sWf[k0 * COUTV + n],       sWf[(k0 + 1) * COUTV + n]);
                __half2 b1 = __floats2half2_rn(sWf[(k0 + 8) * COUTV + n], sWf[(k0 + 9) * COUTV + n]);
                Bf[nt][kt][0] = *(uint32_t*)&b0;
                Bf[nt][kt][1] = *(uint32_t*)&b1;
            }
            biasf[nt].x = bias_out[nt * 8 + kq];
            biasf[nt].y = bias_out[nt * 8 + kq + 1];
        }
    }

    // ldmatrix.x2 source addresses: lanes 0-7 rows 0-7 (+col off), lanes 8-15 rows 0-7 at +16B.
    uint32_t a_base;
    {
        int arow = (lane < 8) ? lane : ((lane < 16) ? (lane - 8) : 0);
        int acol = (lane >= 8 && lane < 16) ? 16 : 0;
        char* ap = (char*)(aggsh + warp * (8 * AG_STRIDE_W)) + arow * 80 + acol;
        a_base = (uint32_t)__cvta_generic_to_shared(ap);
    }
    uint32_t* awarp = aggsh + warp * (8 * AG_STRIDE_W);

    long long R = (long long)B * N;
    long long chunk = (R + gridDim.x - 1) / gridDim.x;
    long long r0 = (long long)blockIdx.x * chunk;
    long long r1 = r0 + chunk; if (r1 > R) r1 = R;
    if (r0 >= r1) return;

    // Prologue: fill up to NBUF batches.
    ll s_ahead = r0;
    for (int k = 0; k < NBUF && s_ahead < r1; k++) {
        if (tid == 0) {
            ll se = ((s_ahead / N) + 1) * (ll)N; if (se > r1) se = r1;
            uint32_t bytes = (uint32_t)((se - s_ahead < NRB ? se - s_ahead : NRB) * ROWB);
            mbar_expect_tx(mb_base + k * 8, bytes);
            tma_bulk(fbuf_sa + k * (NRB * ROWB), f_in + s_ahead * ROWF, bytes, mb_base + k * 8);
        }
        s_ahead = nextb(s_ahead, r1, N);
    }

    ull      Mp[16];
    uint32_t ip[8];
    int bcur = -1;
    uint32_t fpar = 0, epar = 0;

    ll s = r0;
    int bi = 0;
    while (s < r1) {
        ll segend = ((s / N) + 1) * (ll)N; if (segend > r1) segend = r1;
        int b = (int)(s / N);
        if (b != bcur) {
            bcur = b;
            int og = obase + ogl;
            const ull* mp = (const ull*)(g_Mw + (size_t)(b * OPAD + og) * KMAX * CINV);
            #pragma unroll
            for (int k = 0; k < 16; k++) Mp[k] = mp[k * (CINV / 2) + hl];
            const uint32_t* q = (const uint32_t*)&g_selo[(b * OPAD + og) * KMAX];
            #pragma unroll
            for (int j = 0; j < 8; j++) ip[j] = q[j];
        }
        const int nrows = (int)((segend - s) < NRB ? (segend - s) : NRB);
        const int buf = bi & (NBUF - 1);

        mbar_wait(mb_base + buf * 8, (fpar >> buf) & 1);

        phase1((const char*)(fbuf + buf * (NRB * ROWF)), awarp, Mp, ip, ho, hl);
        __syncwarp();
        if (lane == 0) mbar_arrive(mb_base + 32 + buf * 8);

        if (tid == 0 && s_ahead < r1) {
            mbar_wait(mb_base + 32 + buf * 8, (epar >> buf) & 1);
            epar ^= (1u << buf);
            ll se2 = ((s_ahead / N) + 1) * (ll)N; if (se2 > r1) se2 = r1;
            uint32_t bytes = (uint32_t)((se2 - s_ahead < NRB ? se2 - s_ahead : NRB) * ROWB);
            mbar_expect_tx(mb_base + buf * 8, bytes);
            tma_bulk(fbuf_sa + buf * (NRB * ROWB), f_in + s_ahead * ROWF, bytes, mb_base + buf * 8);
            s_ahead = nextb(s_ahead, r1, N);
        }
        fpar ^= (1u << buf);

        // ---- Phase 2: HMMA, A rows 0-7 valid (k 0..15 in {a0,a2}, k 16..31 in {a4,a6}).
        uint32_t a0, a2, a4, a6;
        asm volatile("ldmatrix.sync.aligned.m8n8.x2.shared.b16 {%0,%1}, [%2];"
                     : "=r"(a0), "=r"(a2) : "r"(a_base));
        asm volatile("ldmatrix.sync.aligned.m8n8.x2.shared.b16 {%0,%1}, [%2];"
                     : "=r"(a4), "=r"(a6) : "r"(a_base + 32));
        const uint32_t z = 0;

        const int gr   = lane >> 2;            // Mrow 0..7
        const int ncol = (lane & 3) * 2;
        const int og   = obase + warp * 2 + (gr >> 2);
        const int rr   = gr & 3;
        const bool dostore = (rr < nrows) && (og < QOUT);
        float* rowp = out + (s + rr) * (QOUT * COUTV);

        #pragma unroll
        for (int nt = 0; nt < 4; nt++) {
            float d0 = biasf[nt].x, d1 = biasf[nt].y, d2 = 0.f, d3 = 0.f;
            asm volatile("mma.sync.aligned.m16n8k16.row.col.f32.f16.f16.f32 "
                         "{%0,%1,%2,%3}, {%4,%5,%6,%7}, {%8,%9}, {%0,%1,%2,%3};"
                         : "+f"(d0), "+f"(d1), "+f"(d2), "+f"(d3)
                         : "r"(a0), "r"(z), "r"(a2), "r"(z),
                           "r"(Bf[nt][0][0]), "r"(Bf[nt][0][1]));
            asm volatile("mma.sync.aligned.m16n8k16.row.col.f32.f16.f16.f32 "
                         "{%0,%1,%2,%3}, {%4,%5,%6,%7}, {%8,%9}, {%0,%1,%2,%3};"
                         : "+f"(d0), "+f"(d1), "+f"(d2), "+f"(d3)
                         : "r"(a4), "r"(z), "r"(a6), "r"(z),
                           "r"(Bf[nt][1][0]), "r"(Bf[nt][1][1]));
            if (dostore) {
                float2 v; v.x = d0; v.y = d1;
                *(float2*)(rowp + og * COUTV + nt * 8 + ncol) = v;
            }
        }

        s = nextb(s, r1, N);
        bi++;
    }
}

// ---------------------------------------------------------------------------
extern "C" void kernel_launch(void* const* d_in, const int* in_sizes, int n_in,
                              void* d_out, int out_size)
{
    const float* ang_in   = (const float*)d_in[0];
    const float* ang_out  = (const float*)d_in[1];
    const float* f_in     = (const float*)d_in[2];
    const float* W1       = (const float*)d_in[3];
    const float* b1       = (const float*)d_in[4];
    const float* W2       = (const float*)d_in[5];
    const float* b2       = (const float*)d_in[6];
    const float* W3       = (const float*)d_in[7];
    const float* b3       = (const float*)d_in[8];
    const float* Wf       = (const float*)d_in[9];
    const float* bias_out = (const float*)d_in[10];
    float* out = (float*)d_out;

    int B = in_sizes[0] / (QIN * 3);
    int N = in_sizes[2] / (B * QIN * CINV);

    cudaFuncSetAttribute(conv_kernel, cudaFuncAttributeMaxDynamicSharedMemorySize, SMEM_BYTES);

    prep_kernel<<<B * OPAD, 128>>>(ang_in, ang_out, W1, b1, W2, b2, W3, b3, B);

    int nsm = 148;
    cudaDeviceGetAttribute(&nsm, cudaDevAttrMultiProcessorCount, 0);
    int gx = nsm / 2; if (gx < 1) gx = 1;
    dim3 grid(gx, 2);
    conv_kernel<<<grid, NTH, SMEM_BYTES>>>(f_in, Wf, bias_out, out, B, N);
}